// round 12
// baseline (speedup 1.0000x reference)
#include <cuda_runtime.h>
#include <cuda_fp16.h>
#include <math.h>
#include <stdint.h>

#define B_   4
#define S_   2048
#define D_   2048
#define H_   16
#define HD_  128
#define DFF_ 8192
#define M_   (B_*S_)

// ---------------- scratch (static device globals; no allocation) ----------------
__device__ __half g_h  [(size_t)M_*D_];
__device__ __half g_q  [(size_t)M_*D_];
__device__ __half g_k  [(size_t)M_*D_];
__device__ __half g_vt [(size_t)M_*D_];     // V^T: [b][d][s]
__device__ __half g_o  [(size_t)M_*D_];
__device__ float  g_x1 [(size_t)M_*D_];
__device__ __half g_mid[(size_t)M_*DFF_];
__device__ __half g_wqT [(size_t)D_*D_];
__device__ __half g_wkT [(size_t)D_*D_];
__device__ __half g_wvT [(size_t)D_*D_];
__device__ __half g_woT [(size_t)D_*D_];
__device__ __half g_fc1T[(size_t)DFF_*D_];   // [DFF, D]
__device__ __half g_fc2T[(size_t)D_*DFF_];   // [D, DFF]

__device__ __forceinline__ float gelu_new_f(float x) {
    const float c = 0.7978845608028654f;
    return 0.5f * x * (1.0f + tanhf(c * (x + 0.044715f * x * x * x)));
}

__device__ __forceinline__ uint32_t h2_as_u32(__half2 h) {
    uint32_t u;
    *(__half2*)&u = h;
    return u;
}

__device__ __forceinline__ uint32_t smem_u32(const void* p) {
    uint32_t a;
    asm("{ .reg .u64 t; cvta.to.shared.u64 t, %1; cvt.u32.u64 %0, t; }" : "=r"(a) : "l"(p));
    return a;
}

__device__ __forceinline__ void mma_fp16(float* d,
                                         uint32_t a0, uint32_t a1, uint32_t a2, uint32_t a3,
                                         uint32_t b0, uint32_t b1) {
    asm volatile("mma.sync.aligned.m16n8k16.row.col.f32.f16.f16.f32 "
                 "{%0,%1,%2,%3}, {%4,%5,%6,%7}, {%8,%9}, {%0,%1,%2,%3};"
                 : "+f"(d[0]), "+f"(d[1]), "+f"(d[2]), "+f"(d[3])
                 : "r"(a0), "r"(a1), "r"(a2), "r"(a3), "r"(b0), "r"(b1));
}

__device__ __forceinline__ void ldsm_x4(uint32_t& r0, uint32_t& r1, uint32_t& r2, uint32_t& r3,
                                        uint32_t addr) {
    asm volatile("ldmatrix.sync.aligned.m8n8.x4.shared.b16 {%0,%1,%2,%3}, [%4];"
                 : "=r"(r0), "=r"(r1), "=r"(r2), "=r"(r3) : "r"(addr));
}

#define CP_ASYNC16(dst_u32, src_ptr) \
    asm volatile("cp.async.cg.shared.global [%0], [%1], 16;" :: "r"(dst_u32), "l"(src_ptr))
#define CP_COMMIT() asm volatile("cp.async.commit_group;" ::: "memory")
#define CP_WAIT1()  asm volatile("cp.async.wait_group 1;" ::: "memory")
#define CP_WAIT0()  asm volatile("cp.async.wait_group 0;" ::: "memory")

// ---------------- LayerNorm: fp32 in -> fp16 out (feeds GEMMs only) ----------------
__global__ __launch_bounds__(256) void ln_kernel(const float* __restrict__ x,
                                                 const float* __restrict__ w,
                                                 const float* __restrict__ b,
                                                 __half* __restrict__ out) {
    __shared__ float redA[8], redB[8];
    size_t row = blockIdx.x;
    const float* xr = x + row * D_;
    __half2* orow = (__half2*)(out + row * D_);
    int t = threadIdx.x, lane = t & 31, wid = t >> 5;
    float v[8];
    float4 f0 = *(const float4*)(xr + t * 4);
    float4 f1 = *(const float4*)(xr + 1024 + t * 4);
    v[0]=f0.x; v[1]=f0.y; v[2]=f0.z; v[3]=f0.w;
    v[4]=f1.x; v[5]=f1.y; v[6]=f1.z; v[7]=f1.w;
    float s = 0.f;
    #pragma unroll
    for (int i = 0; i < 8; i++) s += v[i];
    #pragma unroll
    for (int o2 = 16; o2 > 0; o2 >>= 1) s += __shfl_xor_sync(0xffffffffu, s, o2);
    if (!lane) redA[wid] = s;
    __syncthreads();
    float tot = 0.f;
    #pragma unroll
    for (int i = 0; i < 8; i++) tot += redA[i];
    float mu = tot * (1.0f / (float)D_);
    float sq = 0.f;
    #pragma unroll
    for (int i = 0; i < 8; i++) { float d = v[i] - mu; sq += d * d; }
    #pragma unroll
    for (int o2 = 16; o2 > 0; o2 >>= 1) sq += __shfl_xor_sync(0xffffffffu, sq, o2);
    if (!lane) redB[wid] = sq;
    __syncthreads();
    float var = 0.f;
    #pragma unroll
    for (int i = 0; i < 8; i++) var += redB[i];
    var *= (1.0f / (float)D_);
    float inv = rsqrtf(var + 1e-5f);
    float4 w0 = *(const float4*)(w + t * 4);
    float4 w1 = *(const float4*)(w + 1024 + t * 4);
    float4 b0 = *(const float4*)(b + t * 4);
    float4 b1 = *(const float4*)(b + 1024 + t * 4);
    orow[t*2+0]   = __floats2half2_rn((v[0]-mu)*inv*w0.x + b0.x, (v[1]-mu)*inv*w0.y + b0.y);
    orow[t*2+1]   = __floats2half2_rn((v[2]-mu)*inv*w0.z + b0.z, (v[3]-mu)*inv*w0.w + b0.w);
    orow[512+t*2] = __floats2half2_rn((v[4]-mu)*inv*w1.x + b1.x, (v[5]-mu)*inv*w1.y + b1.y);
    orow[513+t*2] = __floats2half2_rn((v[6]-mu)*inv*w1.z + b1.z, (v[7]-mu)*inv*w1.w + b1.w);
}

// ---------------- transpose [R,C] fp32 -> [C,R] fp16 ----------------
__global__ __launch_bounds__(256) void transpose_k(const float* __restrict__ in,
                                                   __half* __restrict__ out, int R, int C) {
    __shared__ float t[32][33];
    int bx = blockIdx.x * 32, by = blockIdx.y * 32;
    int x = bx + threadIdx.x;
    #pragma unroll
    for (int i = 0; i < 32; i += 8)
        t[threadIdx.y + i][threadIdx.x] = in[(size_t)(by + threadIdx.y + i) * C + x];
    __syncthreads();
    int x2 = by + threadIdx.x;
    #pragma unroll
    for (int i = 0; i < 32; i += 8)
        out[(size_t)(bx + threadIdx.y + i) * R + x2] = __float2half_rn(t[threadIdx.x][threadIdx.y + i]);
}

// ---------------- fused flash attention v2 ----------------
// grid (S/64, B*H), 128 threads (4 warps). CTA: 64 q rows; KV chunks of 64.
// Warps partition q rows (warp w owns rows [w*16, w*16+16)). Softmax per-row in-thread
// + quad shuffles. P staged through smem as fp16, ldmatrix'd back for PV (hgemm A layout).
// V read from g_vt [b][d][s] so PV's B operand is row-major [hd][kv] (hgemm B layout).
#define QR 68   // u32 row stride for 128-half rows (Qs, Ks)
#define PR 36   // u32 row stride for  64-half rows (Vs, Ps)
__global__ __launch_bounds__(128, 3) void flash2(
    const __half* __restrict__ q, const __half* __restrict__ k,
    const __half* __restrict__ vt, __half* __restrict__ o)
{
    extern __shared__ uint32_t fs[];
    uint32_t* Qs = fs;                 // 64*68 = 4352
    uint32_t* Ks = fs + 4352;          // 64*68 = 4352
    uint32_t* Vs = fs + 8704;          // 128*36 = 4608
    uint32_t* Ps = fs + 13312;         // 64*36 = 2304   (total 15616 u32 = 62464 B)

    int bh = blockIdx.y;
    int bb = bh >> 4, hh = bh & 15;
    size_t base = ((size_t)bb * S_) * D_ + (size_t)hh * HD_;
    const __half* vbase = vt + ((size_t)bb * D_ + (size_t)hh * HD_) * S_;
    int q0 = blockIdx.x * 64;

    int tid = threadIdx.x;
    int w = tid >> 5, lane = tid & 31;
    int g = lane >> 2, tig = lane & 3;
    const uint32_t FULL = 0xffffffffu;

#define ISSUE_K(kv0) do {                                                       \
    _Pragma("unroll")                                                           \
    for (int i_ = 0; i_ < 8; i_++) {                                            \
        int idx_ = i_ * 128 + tid;                                              \
        int row_ = idx_ >> 4, c_ = idx_ & 15;                                   \
        CP_ASYNC16(smem_u32(Ks + row_ * QR + c_ * 4),                           \
                   k + base + (size_t)((kv0) + row_) * D_ + c_ * 8);            \
    }                                                                           \
} while (0)
#define ISSUE_V(kv0) do {                                                       \
    _Pragma("unroll")                                                           \
    for (int i_ = 0; i_ < 8; i_++) {                                            \
        int idx_ = i_ * 128 + tid;                                              \
        int row_ = idx_ >> 3, c_ = idx_ & 7;                                    \
        CP_ASYNC16(smem_u32(Vs + row_ * PR + c_ * 4),                           \
                   vbase + (size_t)row_ * S_ + (kv0) + c_ * 8);                 \
    }                                                                           \
} while (0)

    // load Q (once) + K0 + V0, single commit group
    #pragma unroll
    for (int i = 0; i < 8; i++) {
        int idx = i * 128 + tid;
        int row = idx >> 4, c = idx & 15;
        CP_ASYNC16(smem_u32(Qs + row * QR + c * 4),
                   q + base + (size_t)(q0 + row) * D_ + c * 8);
    }
    ISSUE_K(0);
    ISSUE_V(0);
    CP_COMMIT();

    // ldmatrix lane addresses (byte offsets)
    uint32_t Aaddr = smem_u32(Qs) + ((w * 16 + (lane & 15)) * QR + (lane >> 4) * 4) * 4;
    uint32_t Baddr = smem_u32(Ks) + (((lane >> 4) * 8 + (lane & 7)) * QR + ((lane >> 3) & 1) * 4) * 4;
    uint32_t Paddr = smem_u32(Ps) + ((w * 16 + (lane & 15)) * PR + (lane >> 4) * 4) * 4;
    uint32_t Vaddr = smem_u32(Vs) + (((lane >> 4) * 8 + (lane & 7)) * PR + ((lane >> 3) & 1) * 4) * 4;

    float oacc[16][4];
    #pragma unroll
    for (int i = 0; i < 16; i++) { oacc[i][0]=0.f; oacc[i][1]=0.f; oacc[i][2]=0.f; oacc[i][3]=0.f; }
    float m0 = -1e30f, m1 = -1e30f, l0 = 0.f, l1 = 0.f;

    for (int ci = 0; ci < S_ / 64; ci++) {
        CP_WAIT0();
        __syncthreads();

        // ---- S = Q K^T : warp tile 16q x 64kv, contraction hd=128 ----
        float sacc[8][4];
        #pragma unroll
        for (int nt = 0; nt < 8; nt++) { sacc[nt][0]=0.f; sacc[nt][1]=0.f; sacc[nt][2]=0.f; sacc[nt][3]=0.f; }
        #pragma unroll
        for (int kk = 0; kk < 8; kk++) {
            uint32_t a0, a1, a2, a3;
            ldsm_x4(a0, a1, a2, a3, Aaddr + kk * 32);
            uint32_t bf[8][2];
            #pragma unroll
            for (int p = 0; p < 4; p++)
                ldsm_x4(bf[2*p][0], bf[2*p][1], bf[2*p+1][0], bf[2*p+1][1],
                        Baddr + p * (16 * QR * 4) + kk * 32);
            #pragma unroll
            for (int nt = 0; nt < 8; nt++)
                mma_fp16(sacc[nt], a0, a1, a2, a3, bf[nt][0], bf[nt][1]);
        }
        const float scl = 0.08838834764831845f;
        #pragma unroll
        for (int nt = 0; nt < 8; nt++) {
            sacc[nt][0] *= scl; sacc[nt][1] *= scl; sacc[nt][2] *= scl; sacc[nt][3] *= scl;
        }

        // ---- online softmax (rows w*16+g and w*16+g+8) ----
        float mx0 = -1e30f, mx1 = -1e30f;
        #pragma unroll
        for (int nt = 0; nt < 8; nt++) {
            mx0 = fmaxf(mx0, fmaxf(sacc[nt][0], sacc[nt][1]));
            mx1 = fmaxf(mx1, fmaxf(sacc[nt][2], sacc[nt][3]));
        }
        mx0 = fmaxf(mx0, __shfl_xor_sync(FULL, mx0, 1));
        mx0 = fmaxf(mx0, __shfl_xor_sync(FULL, mx0, 2));
        mx1 = fmaxf(mx1, __shfl_xor_sync(FULL, mx1, 1));
        mx1 = fmaxf(mx1, __shfl_xor_sync(FULL, mx1, 2));
        float mn0 = fmaxf(m0, mx0), mn1 = fmaxf(m1, mx1);
        float cr0 = __expf(m0 - mn0), cr1 = __expf(m1 - mn1);
        m0 = mn0; m1 = mn1;
        float rs0 = 0.f, rs1 = 0.f;
        #pragma unroll
        for (int nt = 0; nt < 8; nt++) {
            sacc[nt][0] = __expf(sacc[nt][0] - mn0); rs0 += sacc[nt][0];
            sacc[nt][1] = __expf(sacc[nt][1] - mn0); rs0 += sacc[nt][1];
            sacc[nt][2] = __expf(sacc[nt][2] - mn1); rs1 += sacc[nt][2];
            sacc[nt][3] = __expf(sacc[nt][3] - mn1); rs1 += sacc[nt][3];
        }
        rs0 += __shfl_xor_sync(FULL, rs0, 1);  rs0 += __shfl_xor_sync(FULL, rs0, 2);
        rs1 += __shfl_xor_sync(FULL, rs1, 1);  rs1 += __shfl_xor_sync(FULL, rs1, 2);
        l0 = l0 * cr0 + rs0;  l1 = l1 * cr1 + rs1;
        #pragma unroll
        for (int nt = 0; nt < 16; nt++) {
            oacc[nt][0] *= cr0; oacc[nt][1] *= cr0; oacc[nt][2] *= cr1; oacc[nt][3] *= cr1;
        }

        // ---- store P (fp16) to Ps ----
        {
            int r0i = w * 16 + g;
            #pragma unroll
            for (int nt = 0; nt < 8; nt++) {
                Ps[r0i * PR + nt * 4 + tig]       = h2_as_u32(__floats2half2_rn(sacc[nt][0], sacc[nt][1]));
                Ps[(r0i + 8) * PR + nt * 4 + tig] = h2_as_u32(__floats2half2_rn(sacc[nt][2], sacc[nt][3]));
            }
        }
        __syncthreads();                     // Ps visible; Ks free
        if (ci + 1 < S_ / 64) { ISSUE_K((ci + 1) * 64); CP_COMMIT(); }

        // ---- O += P V : warp tile 16q x 128hd, contraction kv=64 ----
        #pragma unroll
        for (int kk = 0; kk < 4; kk++) {
            uint32_t a0, a1, a2, a3;
            ldsm_x4(a0, a1, a2, a3, Paddr + kk * 32);
            uint32_t bf[16][2];
            #pragma unroll
            for (int p = 0; p < 8; p++)
                ldsm_x4(bf[2*p][0], bf[2*p][1], bf[2*p+1][0], bf[2*p+1][1],
                        Vaddr + p * (16 * PR * 4) + kk * 32);
            #pragma unroll
            for (int nt = 0; nt < 16; nt++)
                mma_fp16(oacc[nt], a0, a1, a2, a3, bf[nt][0], bf[nt][1]);
        }
        __syncthreads();                     // Vs, Ps free
        if (ci + 1 < S_ / 64) { ISSUE_V((ci + 1) * 64); CP_COMMIT(); }
    }
#undef ISSUE_K
#undef ISSUE_V

    // ---- epilogue: normalize, fp16 store to o [b,s,h*hd] ----
    float inv0 = 1.f / l0, inv1 = 1.f / l1;
    int r0i = q0 + w * 16 + g;
    #pragma unroll
    for (int nt = 0; nt < 16; nt++) {
        int col = nt * 8 + 2 * tig;
        *(__half2*)(o + base + (size_t)r0i * D_ + col)       = __floats2half2_rn(oacc[nt][0]*inv0, oacc[nt][1]*inv0);
        *(__half2*)(o + base + (size_t)(r0i + 8) * D_ + col) = __floats2half2_rn(oacc[nt][2]*inv1, oacc[nt][3]*inv1);
    }
}

// ---------------- fp16 mma.sync GEMM (R7-proven 2-stage config) ----------------
// EPI: 0=alpha*acc ; 1=gelu(acc+bias) ; 2=acc+resid ; 3=acc+bias+resid ; 4=V^T scatter
#define W32 36
template<int EPI, bool OUTH>
__global__ __launch_bounds__(256, 2) void hgemm(
    const __half* __restrict__ A, int lda, long long sA1, long long sA2,
    const __half* __restrict__ Bm, int ldb, long long sB1, long long sB2,
    void* __restrict__ Cv, int ldc, long long sC1, long long sC2,
    int K, float alpha,
    const float* __restrict__ bias,
    const float* __restrict__ resid,
    int Hdiv)
{
    const int ASZ = 128 * W32;
    const int STG = 2 * ASZ;
    extern __shared__ uint32_t sm[];
    uint32_t* Abuf[2] = { sm,       sm + STG };
    uint32_t* Bbuf[2] = { sm + ASZ, sm + STG + ASZ };

    int z = blockIdx.z;
    int zb = z / Hdiv, zh = z % Hdiv;
    const __half* Ab = A  + (size_t)zb * sA1 + (size_t)zh * sA2;
    const __half* Bb = Bm + (size_t)zb * sB1 + (size_t)zh * sB2;

    int m0 = blockIdx.y * 128;
    int n0 = blockIdx.x * 128;
    int tid = threadIdx.x;
    int wid = tid >> 5, lane = tid & 31;
    int g = lane >> 2, tig = lane & 3;
    int warpM = wid >> 2, warpN = wid & 3;

    const __half* Abase = Ab + (size_t)m0 * lda;
    const __half* Bbase = Bb + (size_t)n0 * ldb;

    int aoff = ((warpM * 64 + (lane & 15)) * W32 + (lane >> 4) * 4) * 4;
    int boff = ((warpN * 32 + (lane >> 4) * 8 + (lane & 7)) * W32 + ((lane >> 3) & 1) * 4) * 4;

    float acc[4][4][4];
    #pragma unroll
    for (int i = 0; i < 4; i++)
        #pragma unroll
        for (int j = 0; j < 4; j++)
            #pragma unroll
            for (int r = 0; r < 4; r++) acc[i][j][r] = 0.f;

    int KT = K >> 6;

#define ISSUE_TILE(kt, bsel) do {                                              \
    const __half* Ag_ = Abase + (size_t)(kt) * 64;                             \
    const __half* Bg_ = Bbase + (size_t)(kt) * 64;                             \
    _Pragma("unroll")                                                          \
    for (int i_ = 0; i_ < 4; i_++) {                                           \
        int idx_ = i_ * 256 + tid;                                             \
        int row_ = idx_ >> 3, c8_ = idx_ & 7;                                  \
        uint32_t da_ = smem_u32(Abuf[bsel] + row_ * W32 + c8_ * 4);            \
        CP_ASYNC16(da_, Ag_ + (size_t)row_ * lda + c8_ * 8);                   \
    }                                                                          \
    _Pragma("unroll")                                                          \
    for (int i_ = 0; i_ < 4; i_++) {                                           \
        int idx_ = i_ * 256 + tid;                                             \
        int row_ = idx_ >> 3, c8_ = idx_ & 7;                                  \
        uint32_t db_ = smem_u32(Bbuf[bsel] + row_ * W32 + c8_ * 4);            \
        CP_ASYNC16(db_, Bg_ + (size_t)row_ * ldb + c8_ * 8);                   \
    }                                                                          \
    CP_COMMIT();                                                               \
} while (0)

    ISSUE_TILE(0, 0);

    for (int kt = 0; kt < KT; kt++) {
        int bsel = kt & 1;
        if (kt + 1 < KT) { ISSUE_TILE(kt + 1, bsel ^ 1); CP_WAIT1(); }
        else             { CP_WAIT0(); }
        __syncthreads();

        uint32_t As_base = smem_u32(Abuf[bsel]) + aoff;
        uint32_t Bs_base = smem_u32(Bbuf[bsel]) + boff;
        #pragma unroll
        for (int kk = 0; kk < 4; kk++) {
            uint32_t As_a = As_base + kk * 32;
            uint32_t Bs_a = Bs_base + kk * 32;
            uint32_t af[4][4];
            #pragma unroll
            for (int mt = 0; mt < 4; mt++)
                ldsm_x4(af[mt][0], af[mt][1], af[mt][2], af[mt][3],
                        As_a + mt * (16 * W32 * 4));
            uint32_t bf[4][2];
            ldsm_x4(bf[0][0], bf[0][1], bf[1][0], bf[1][1], Bs_a);
            ldsm_x4(bf[2][0], bf[2][1], bf[3][0], bf[3][1], Bs_a + 16 * W32 * 4);
            #pragma unroll
            for (int mt = 0; mt < 4; mt++)
                #pragma unroll
                for (int nt = 0; nt < 4; nt++)
                    mma_fp16(acc[mt][nt], af[mt][0], af[mt][1], af[mt][2], af[mt][3],
                             bf[nt][0], bf[nt][1]);
        }
        __syncthreads();
    }
#undef ISSUE_TILE

    float*  Cf = (float*)Cv  + (OUTH ? 0 : ((size_t)zb * sC1 + (size_t)zh * sC2));
    __half* Ch = (__half*)Cv + (OUTH ? ((size_t)zb * sC1 + (size_t)zh * sC2) : 0);
    #pragma unroll
    for (int mt = 0; mt < 4; mt++) {
        #pragma unroll
        for (int nt = 0; nt < 4; nt++) {
            int r0 = m0 + warpM * 64 + mt * 16 + g;
            int cN = n0 + warpN * 32 + nt * 8 + 2 * tig;
            #pragma unroll
            for (int hh = 0; hh < 2; hh++) {
                int rr = r0 + hh * 8;
                float e0 = acc[mt][nt][2 * hh + 0];
                float e1 = acc[mt][nt][2 * hh + 1];
                if (EPI == 0) { e0 *= alpha; e1 *= alpha; }
                if (EPI == 1 || EPI == 3) {
                    float2 bb = *(const float2*)(bias + cN);
                    e0 += bb.x; e1 += bb.y;
                }
                if (EPI == 1) { e0 = gelu_new_f(e0); e1 = gelu_new_f(e1); }
                if (EPI == 2 || EPI == 3) {
                    float2 rv = *(const float2*)(resid + (size_t)rr * ldc + cN);
                    e0 += rv.x; e1 += rv.y;
                }
                if (EPI == 4) {
                    int bidx = rr >> 11;
                    int sloc = rr & (S_ - 1);
                    Ch[((size_t)bidx * D_ + cN) * S_ + sloc]     = __float2half_rn(e0);
                    Ch[((size_t)bidx * D_ + cN + 1) * S_ + sloc] = __float2half_rn(e1);
                } else if (OUTH) {
                    *(__half2*)(Ch + (size_t)rr * ldc + cN) = __floats2half2_rn(e0, e1);
                } else {
                    float2 st; st.x = e0; st.y = e1;
                    *(float2*)(Cf + (size_t)rr * ldc + cN) = st;
                }
            }
        }
    }
}

// ---------------- host ----------------
static const int DSM  = 2 * 2 * 128 * W32 * 4;   // 73728 bytes (hgemm)
static const int FDSM = 15616 * 4;               // 62464 bytes (flash2)

extern "C" void kernel_launch(void* const* d_in, const int* in_sizes, int n_in,
                              void* d_out, int out_size) {
    (void)in_sizes; (void)n_in; (void)out_size;
    const float* x    = (const float*)d_in[0];
    const float* wq   = (const float*)d_in[1];
    const float* wk   = (const float*)d_in[2];
    const float* wv   = (const float*)d_in[3];
    const float* wo   = (const float*)d_in[4];
    const float* ln1w = (const float*)d_in[5];
    const float* ln1b = (const float*)d_in[6];
    const float* ln2w = (const float*)d_in[7];
    const float* ln2b = (const float*)d_in[8];
    const float* fc1w = (const float*)d_in[9];
    const float* fc1b = (const float*)d_in[10];
    const float* fc2w = (const float*)d_in[11];
    const float* fc2b = (const float*)d_in[12];
    float* out = (float*)d_out;

    __half *h, *q, *k, *vt, *o, *mid;
    float *x1;
    __half *wqT, *wkT, *wvT, *woT, *fc1T, *fc2T;
    cudaGetSymbolAddress((void**)&h,    g_h);
    cudaGetSymbolAddress((void**)&q,    g_q);
    cudaGetSymbolAddress((void**)&k,    g_k);
    cudaGetSymbolAddress((void**)&vt,   g_vt);
    cudaGetSymbolAddress((void**)&o,    g_o);
    cudaGetSymbolAddress((void**)&x1,   g_x1);
    cudaGetSymbolAddress((void**)&mid,  g_mid);
    cudaGetSymbolAddress((void**)&wqT,  g_wqT);
    cudaGetSymbolAddress((void**)&wkT,  g_wkT);
    cudaGetSymbolAddress((void**)&wvT,  g_wvT);
    cudaGetSymbolAddress((void**)&woT,  g_woT);
    cudaGetSymbolAddress((void**)&fc1T, g_fc1T);
    cudaGetSymbolAddress((void**)&fc2T, g_fc2T);

    cudaFuncSetAttribute(hgemm<0,true >, cudaFuncAttributeMaxDynamicSharedMemorySize, DSM);
    cudaFuncSetAttribute(hgemm<4,true >, cudaFuncAttributeMaxDynamicSharedMemorySize, DSM);
    cudaFuncSetAttribute(hgemm<2,false>, cudaFuncAttributeMaxDynamicSharedMemorySize, DSM);
    cudaFuncSetAttribute(hgemm<1,true >, cudaFuncAttributeMaxDynamicSharedMemorySize, DSM);
    cudaFuncSetAttribute(hgemm<3,false>, cudaFuncAttributeMaxDynamicSharedMemorySize, DSM);
    cudaFuncSetAttribute(flash2,         cudaFuncAttributeMaxDynamicSharedMemorySize, FDSM);

    dim3 blk(256);
    dim3 tb(32, 8);
    dim3 g1(D_ / 128, M_ / 128, 1);

    // launch order: index 3 = dense Q-projection GEMM (ncu profiles launch idx 3)
    ln_kernel<<<M_, 256>>>(x, ln1w, ln1b, h);                               // 0
    transpose_k<<<dim3(D_/32, D_/32), tb>>>(wq, wqT, D_, D_);               // 1
    transpose_k<<<dim3(D_/32, D_/32), tb>>>(wk, wkT, D_, D_);               // 2
    hgemm<0,true ><<<g1, blk, DSM>>>(h, D_, 0, 0, wqT, D_, 0, 0, q,  D_, 0, 0, D_, 1.f, 0, 0, 1);  // 3 <- profiled
    hgemm<0,true ><<<g1, blk, DSM>>>(h, D_, 0, 0, wkT, D_, 0, 0, k,  D_, 0, 0, D_, 1.f, 0, 0, 1);  // 4
    transpose_k<<<dim3(D_/32, D_/32), tb>>>(wv, wvT, D_, D_);               // 5
    hgemm<4,true ><<<g1, blk, DSM>>>(h, D_, 0, 0, wvT, D_, 0, 0, vt, S_, 0, 0, D_, 1.f, 0, 0, 1);  // 6

    // --- fused flash attention ---
    flash2<<<dim3(S_/64, B_*H_), 128, FDSM>>>(q, k, vt, o);

    // --- out-projection + residual (fp32 residual stream) ---
    transpose_k<<<dim3(D_/32, D_/32), tb>>>(wo, woT, D_, D_);
    hgemm<2,false><<<g1, blk, DSM>>>(o, D_, 0, 0, woT, D_, 0, 0, x1, D_, 0, 0, D_, 1.f, 0, x, 1);

    // --- LN2 ---
    ln_kernel<<<M_, 256>>>(x1, ln2w, ln2b, h);

    // --- FC1 + bias + gelu (fp16 out) ---
    transpose_k<<<dim3(DFF_/32, D_/32), tb>>>(fc1w, fc1T, D_, DFF_);
    dim3 g4(DFF_ / 128, M_ / 128, 1);
    hgemm<1,true ><<<g4, blk, DSM>>>(h, D_, 0, 0, fc1T, D_, 0, 0, mid, DFF_, 0, 0, D_, 1.f, fc1b, 0, 1);

    // --- FC2 + bias + residual -> out (fp32) ---
    transpose_k<<<dim3(D_/32, DFF_/32), tb>>>(fc2w, fc2T, DFF_, D_);
    hgemm<3,false><<<g1, blk, DSM>>>(mid, DFF_, 0, 0, fc2T, DFF_, 0, 0, out, D_, 0, 0, DFF_, 1.f, fc2b, x1, 1);
}

// round 13
// speedup vs baseline: 1.2852x; 1.2852x over previous
#include <cuda_runtime.h>
#include <cuda_fp16.h>
#include <math.h>
#include <stdint.h>

#define B_   4
#define S_   2048
#define D_   2048
#define H_   16
#define HD_  128
#define DFF_ 8192
#define M_   (B_*S_)

// ---------------- scratch (static device globals; no allocation) ----------------
__device__ __half g_h  [(size_t)M_*D_];
__device__ __half g_q  [(size_t)M_*D_];
__device__ __half g_k  [(size_t)M_*D_];
__device__ __half g_vt [(size_t)M_*D_];     // V^T: [b][d][s]
__device__ __half g_o  [(size_t)M_*D_];
__device__ float  g_x1 [(size_t)M_*D_];
__device__ __half g_mid[(size_t)M_*DFF_];
__device__ __half g_sc [(size_t)B_*H_*S_*S_];   // fp16 attention scores
__device__ __half g_p  [(size_t)B_*H_*S_*S_];   // fp16 softmax probs
__device__ __half g_wqT [(size_t)D_*D_];
__device__ __half g_wkT [(size_t)D_*D_];
__device__ __half g_wvT [(size_t)D_*D_];
__device__ __half g_woT [(size_t)D_*D_];
__device__ __half g_fc1T[(size_t)DFF_*D_];   // [DFF, D]
__device__ __half g_fc2T[(size_t)D_*DFF_];   // [D, DFF]

__device__ __forceinline__ float gelu_new_f(float x) {
    const float c = 0.7978845608028654f;
    return 0.5f * x * (1.0f + tanhf(c * (x + 0.044715f * x * x * x)));
}

__device__ __forceinline__ uint32_t smem_u32(const void* p) {
    uint32_t a;
    asm("{ .reg .u64 t; cvta.to.shared.u64 t, %1; cvt.u32.u64 %0, t; }" : "=r"(a) : "l"(p));
    return a;
}

__device__ __forceinline__ void mma_fp16(float* d,
                                         uint32_t a0, uint32_t a1, uint32_t a2, uint32_t a3,
                                         uint32_t b0, uint32_t b1) {
    asm volatile("mma.sync.aligned.m16n8k16.row.col.f32.f16.f16.f32 "
                 "{%0,%1,%2,%3}, {%4,%5,%6,%7}, {%8,%9}, {%0,%1,%2,%3};"
                 : "+f"(d[0]), "+f"(d[1]), "+f"(d[2]), "+f"(d[3])
                 : "r"(a0), "r"(a1), "r"(a2), "r"(a3), "r"(b0), "r"(b1));
}

__device__ __forceinline__ void ldsm_x4(uint32_t& r0, uint32_t& r1, uint32_t& r2, uint32_t& r3,
                                        uint32_t addr) {
    asm volatile("ldmatrix.sync.aligned.m8n8.x4.shared.b16 {%0,%1,%2,%3}, [%4];"
                 : "=r"(r0), "=r"(r1), "=r"(r2), "=r"(r3) : "r"(addr));
}

#define CP_ASYNC16(dst_u32, src_ptr) \
    asm volatile("cp.async.cg.shared.global [%0], [%1], 16;" :: "r"(dst_u32), "l"(src_ptr))
#define CP_COMMIT() asm volatile("cp.async.commit_group;" ::: "memory")
#define CP_WAIT1()  asm volatile("cp.async.wait_group 1;" ::: "memory")
#define CP_WAIT0()  asm volatile("cp.async.wait_group 0;" ::: "memory")

// ---------------- LayerNorm: fp32 in -> fp16 out (feeds GEMMs only) ----------------
__global__ __launch_bounds__(256) void ln_kernel(const float* __restrict__ x,
                                                 const float* __restrict__ w,
                                                 const float* __restrict__ b,
                                                 __half* __restrict__ out) {
    __shared__ float redA[8], redB[8];
    size_t row = blockIdx.x;
    const float* xr = x + row * D_;
    __half2* orow = (__half2*)(out + row * D_);
    int t = threadIdx.x, lane = t & 31, wid = t >> 5;
    float v[8];
    float4 f0 = *(const float4*)(xr + t * 4);
    float4 f1 = *(const float4*)(xr + 1024 + t * 4);
    v[0]=f0.x; v[1]=f0.y; v[2]=f0.z; v[3]=f0.w;
    v[4]=f1.x; v[5]=f1.y; v[6]=f1.z; v[7]=f1.w;
    float s = 0.f;
    #pragma unroll
    for (int i = 0; i < 8; i++) s += v[i];
    #pragma unroll
    for (int o2 = 16; o2 > 0; o2 >>= 1) s += __shfl_xor_sync(0xffffffffu, s, o2);
    if (!lane) redA[wid] = s;
    __syncthreads();
    float tot = 0.f;
    #pragma unroll
    for (int i = 0; i < 8; i++) tot += redA[i];
    float mu = tot * (1.0f / (float)D_);
    float sq = 0.f;
    #pragma unroll
    for (int i = 0; i < 8; i++) { float d = v[i] - mu; sq += d * d; }
    #pragma unroll
    for (int o2 = 16; o2 > 0; o2 >>= 1) sq += __shfl_xor_sync(0xffffffffu, sq, o2);
    if (!lane) redB[wid] = sq;
    __syncthreads();
    float var = 0.f;
    #pragma unroll
    for (int i = 0; i < 8; i++) var += redB[i];
    var *= (1.0f / (float)D_);
    float inv = rsqrtf(var + 1e-5f);
    float4 w0 = *(const float4*)(w + t * 4);
    float4 w1 = *(const float4*)(w + 1024 + t * 4);
    float4 b0 = *(const float4*)(b + t * 4);
    float4 b1 = *(const float4*)(b + 1024 + t * 4);
    orow[t*2+0]   = __floats2half2_rn((v[0]-mu)*inv*w0.x + b0.x, (v[1]-mu)*inv*w0.y + b0.y);
    orow[t*2+1]   = __floats2half2_rn((v[2]-mu)*inv*w0.z + b0.z, (v[3]-mu)*inv*w0.w + b0.w);
    orow[512+t*2] = __floats2half2_rn((v[4]-mu)*inv*w1.x + b1.x, (v[5]-mu)*inv*w1.y + b1.y);
    orow[513+t*2] = __floats2half2_rn((v[6]-mu)*inv*w1.z + b1.z, (v[7]-mu)*inv*w1.w + b1.w);
}

// ---------------- softmax: fp16 scores in -> fp16 probs out ----------------
__global__ __launch_bounds__(256) void softmax_kernel(const __half* __restrict__ sc,
                                                      __half* __restrict__ pout) {
    __shared__ float redA[8], redB[8];
    const __half2* p = (const __half2*)(sc + (size_t)blockIdx.x * S_);
    __half2* po = (__half2*)(pout + (size_t)blockIdx.x * S_);
    int t = threadIdx.x, lane = t & 31, wid = t >> 5;
    float v[8];
    {
        __half2 h0 = p[t*2+0], h1 = p[t*2+1], h2 = p[512+t*2], h3 = p[513+t*2];
        float2 a = __half22float2(h0), b2 = __half22float2(h1);
        float2 c = __half22float2(h2), d2 = __half22float2(h3);
        v[0]=a.x; v[1]=a.y; v[2]=b2.x; v[3]=b2.y;
        v[4]=c.x; v[5]=c.y; v[6]=d2.x; v[7]=d2.y;
    }
    float mx = v[0];
    #pragma unroll
    for (int i = 1; i < 8; i++) mx = fmaxf(mx, v[i]);
    #pragma unroll
    for (int o2 = 16; o2 > 0; o2 >>= 1) mx = fmaxf(mx, __shfl_xor_sync(0xffffffffu, mx, o2));
    if (!lane) redA[wid] = mx;
    __syncthreads();
    float gmx = redA[0];
    #pragma unroll
    for (int i = 1; i < 8; i++) gmx = fmaxf(gmx, redA[i]);
    float s = 0.f;
    #pragma unroll
    for (int i = 0; i < 8; i++) { v[i] = __expf(v[i] - gmx); s += v[i]; }
    #pragma unroll
    for (int o2 = 16; o2 > 0; o2 >>= 1) s += __shfl_xor_sync(0xffffffffu, s, o2);
    if (!lane) redB[wid] = s;
    __syncthreads();
    float tot = 0.f;
    #pragma unroll
    for (int i = 0; i < 8; i++) tot += redB[i];
    float inv = 1.0f / tot;
    po[t*2+0]   = __floats2half2_rn(v[0]*inv, v[1]*inv);
    po[t*2+1]   = __floats2half2_rn(v[2]*inv, v[3]*inv);
    po[512+t*2] = __floats2half2_rn(v[4]*inv, v[5]*inv);
    po[513+t*2] = __floats2half2_rn(v[6]*inv, v[7]*inv);
}

// ---------------- transpose [R,C] fp32 -> [C,R] fp16 ----------------
__global__ __launch_bounds__(256) void transpose_k(const float* __restrict__ in,
                                                   __half* __restrict__ out, int R, int C) {
    __shared__ float t[32][33];
    int bx = blockIdx.x * 32, by = blockIdx.y * 32;
    int x = bx + threadIdx.x;
    #pragma unroll
    for (int i = 0; i < 32; i += 8)
        t[threadIdx.y + i][threadIdx.x] = in[(size_t)(by + threadIdx.y + i) * C + x];
    __syncthreads();
    int x2 = by + threadIdx.x;
    #pragma unroll
    for (int i = 0; i < 32; i += 8)
        out[(size_t)(bx + threadIdx.y + i) * R + x2] = __float2half_rn(t[threadIdx.x][threadIdx.y + i]);
}

// ---------------- fp16 mma.sync GEMM v2: 128 threads, 64x64 warp tiles, 3 CTA/SM ----
// C[M,N] = epi(alpha * A[M,K] @ B[N,K]^T). CTA tile 128x128, K-tile 64 halves,
// 2-stage cp.async. 4 warps in 2x2 grid, warp tile 64x64 (mt=4, nt=8), m16n8k16.
// EPI: 0=alpha*acc ; 1=gelu(acc+bias) ; 2=acc+resid ; 3=acc+bias+resid ; 4=V^T scatter
// OUTH: C is __half (else float)
#define W32 36   // smem row stride in u32 (64 halves data + pad; conflict-free)
template<int EPI, bool OUTH>
__global__ __launch_bounds__(128, 3) void hgemm(
    const __half* __restrict__ A, int lda, long long sA1, long long sA2,
    const __half* __restrict__ Bm, int ldb, long long sB1, long long sB2,
    void* __restrict__ Cv, int ldc, long long sC1, long long sC2,
    int K, float alpha,
    const float* __restrict__ bias,
    const float* __restrict__ resid,
    int Hdiv)
{
    const int ASZ = 128 * W32;           // u32 per A stage
    const int STG = 2 * ASZ;             // u32 per stage (A+B)
    extern __shared__ uint32_t sm[];
    uint32_t* Abuf[2] = { sm,       sm + STG };
    uint32_t* Bbuf[2] = { sm + ASZ, sm + STG + ASZ };

    int z = blockIdx.z;
    int zb = z / Hdiv, zh = z % Hdiv;
    const __half* Ab = A  + (size_t)zb * sA1 + (size_t)zh * sA2;
    const __half* Bb = Bm + (size_t)zb * sB1 + (size_t)zh * sB2;

    int m0 = blockIdx.y * 128;
    int n0 = blockIdx.x * 128;
    int tid = threadIdx.x;
    int wid = tid >> 5, lane = tid & 31;
    int g = lane >> 2, tig = lane & 3;
    int warpM = wid >> 1, warpN = wid & 1;     // 2 x 2, warp tile 64x64

    const __half* Abase = Ab + (size_t)m0 * lda;
    const __half* Bbase = Bb + (size_t)n0 * ldb;

    // ldmatrix per-lane byte offsets (within a stage buffer)
    int aoff = ((warpM * 64 + (lane & 15)) * W32 + (lane >> 4) * 4) * 4;
    int boff = ((warpN * 64 + (lane >> 4) * 8 + (lane & 7)) * W32 + ((lane >> 3) & 1) * 4) * 4;

    float acc[4][8][4];
    #pragma unroll
    for (int i = 0; i < 4; i++)
        #pragma unroll
        for (int j = 0; j < 8; j++)
            #pragma unroll
            for (int r = 0; r < 4; r++) acc[i][j][r] = 0.f;

    int KT = K >> 6;   // 64 halves per tile

#define ISSUE_TILE(kt, bsel) do {                                              \
    const __half* Ag_ = Abase + (size_t)(kt) * 64;                             \
    const __half* Bg_ = Bbase + (size_t)(kt) * 64;                             \
    _Pragma("unroll")                                                          \
    for (int i_ = 0; i_ < 8; i_++) {                                           \
        int idx_ = i_ * 128 + tid;                                             \
        int row_ = idx_ >> 3, c8_ = idx_ & 7;                                  \
        uint32_t da_ = smem_u32(Abuf[bsel] + row_ * W32 + c8_ * 4);            \
        CP_ASYNC16(da_, Ag_ + (size_t)row_ * lda + c8_ * 8);                   \
    }                                                                          \
    _Pragma("unroll")                                                          \
    for (int i_ = 0; i_ < 8; i_++) {                                           \
        int idx_ = i_ * 128 + tid;                                             \
        int row_ = idx_ >> 3, c8_ = idx_ & 7;                                  \
        uint32_t db_ = smem_u32(Bbuf[bsel] + row_ * W32 + c8_ * 4);            \
        CP_ASYNC16(db_, Bg_ + (size_t)row_ * ldb + c8_ * 8);                   \
    }                                                                          \
    CP_COMMIT();                                                               \
} while (0)

    ISSUE_TILE(0, 0);

    for (int kt = 0; kt < KT; kt++) {
        int bsel = kt & 1;
        if (kt + 1 < KT) { ISSUE_TILE(kt + 1, bsel ^ 1); CP_WAIT1(); }
        else             { CP_WAIT0(); }
        __syncthreads();

        uint32_t As_base = smem_u32(Abuf[bsel]) + aoff;
        uint32_t Bs_base = smem_u32(Bbuf[bsel]) + boff;
        #pragma unroll
        for (int kk = 0; kk < 4; kk++) {        // 4 x k16 = 64 halves
            uint32_t As_a = As_base + kk * 32;
            uint32_t Bs_a = Bs_base + kk * 32;
            uint32_t af[4][4];
            #pragma unroll
            for (int mt = 0; mt < 4; mt++)
                ldsm_x4(af[mt][0], af[mt][1], af[mt][2], af[mt][3],
                        As_a + mt * (16 * W32 * 4));
            uint32_t bf[8][2];
            #pragma unroll
            for (int p = 0; p < 4; p++)
                ldsm_x4(bf[2*p][0], bf[2*p][1], bf[2*p+1][0], bf[2*p+1][1],
                        Bs_a + p * (16 * W32 * 4));
            #pragma unroll
            for (int mt = 0; mt < 4; mt++)
                #pragma unroll
                for (int nt = 0; nt < 8; nt++)
                    mma_fp16(acc[mt][nt], af[mt][0], af[mt][1], af[mt][2], af[mt][3],
                             bf[nt][0], bf[nt][1]);
        }
        __syncthreads();
    }
#undef ISSUE_TILE

    // ---- epilogue ----
    float*  Cf = (float*)Cv  + (OUTH ? 0 : ((size_t)zb * sC1 + (size_t)zh * sC2));
    __half* Ch = (__half*)Cv + (OUTH ? ((size_t)zb * sC1 + (size_t)zh * sC2) : 0);
    #pragma unroll
    for (int mt = 0; mt < 4; mt++) {
        #pragma unroll
        for (int nt = 0; nt < 8; nt++) {
            int r0 = m0 + warpM * 64 + mt * 16 + g;
            int cN = n0 + warpN * 64 + nt * 8 + 2 * tig;
            #pragma unroll
            for (int hh = 0; hh < 2; hh++) {
                int rr = r0 + hh * 8;
                float e0 = acc[mt][nt][2 * hh + 0];
                float e1 = acc[mt][nt][2 * hh + 1];
                if (EPI == 0) { e0 *= alpha; e1 *= alpha; }
                if (EPI == 1 || EPI == 3) {
                    float2 bb = *(const float2*)(bias + cN);
                    e0 += bb.x; e1 += bb.y;
                }
                if (EPI == 1) { e0 = gelu_new_f(e0); e1 = gelu_new_f(e1); }
                if (EPI == 2 || EPI == 3) {
                    float2 rv = *(const float2*)(resid + (size_t)rr * ldc + cN);
                    e0 += rv.x; e1 += rv.y;
                }
                if (EPI == 4) {
                    int bidx = rr >> 11;            // rr / S_
                    int sloc = rr & (S_ - 1);
                    Ch[((size_t)bidx * D_ + cN) * S_ + sloc]     = __float2half_rn(e0);
                    Ch[((size_t)bidx * D_ + cN + 1) * S_ + sloc] = __float2half_rn(e1);
                } else if (OUTH) {
                    *(__half2*)(Ch + (size_t)rr * ldc + cN) = __floats2half2_rn(e0, e1);
                } else {
                    float2 st; st.x = e0; st.y = e1;
                    *(float2*)(Cf + (size_t)rr * ldc + cN) = st;
                }
            }
        }
    }
}

// ---------------- host ----------------
static const int DSM = 2 * 2 * 128 * W32 * 4;   // 73728 bytes

extern "C" void kernel_launch(void* const* d_in, const int* in_sizes, int n_in,
                              void* d_out, int out_size) {
    (void)in_sizes; (void)n_in; (void)out_size;
    const float* x    = (const float*)d_in[0];
    const float* wq   = (const float*)d_in[1];
    const float* wk   = (const float*)d_in[2];
    const float* wv   = (const float*)d_in[3];
    const float* wo   = (const float*)d_in[4];
    const float* ln1w = (const float*)d_in[5];
    const float* ln1b = (const float*)d_in[6];
    const float* ln2w = (const float*)d_in[7];
    const float* ln2b = (const float*)d_in[8];
    const float* fc1w = (const float*)d_in[9];
    const float* fc1b = (const float*)d_in[10];
    const float* fc2w = (const float*)d_in[11];
    const float* fc2b = (const float*)d_in[12];
    float* out = (float*)d_out;

    __half *h, *q, *k, *vt, *o, *mid, *p, *sc;
    float *x1;
    __half *wqT, *wkT, *wvT, *woT, *fc1T, *fc2T;
    cudaGetSymbolAddress((void**)&h,    g_h);
    cudaGetSymbolAddress((void**)&q,    g_q);
    cudaGetSymbolAddress((void**)&k,    g_k);
    cudaGetSymbolAddress((void**)&vt,   g_vt);
    cudaGetSymbolAddress((void**)&o,    g_o);
    cudaGetSymbolAddress((void**)&x1,   g_x1);
    cudaGetSymbolAddress((void**)&mid,  g_mid);
    cudaGetSymbolAddress((void**)&sc,   g_sc);
    cudaGetSymbolAddress((void**)&p,    g_p);
    cudaGetSymbolAddress((void**)&wqT,  g_wqT);
    cudaGetSymbolAddress((void**)&wkT,  g_wkT);
    cudaGetSymbolAddress((void**)&wvT,  g_wvT);
    cudaGetSymbolAddress((void**)&woT,  g_woT);
    cudaGetSymbolAddress((void**)&fc1T, g_fc1T);
    cudaGetSymbolAddress((void**)&fc2T, g_fc2T);

    cudaFuncSetAttribute(hgemm<0,true >, cudaFuncAttributeMaxDynamicSharedMemorySize, DSM);
    cudaFuncSetAttribute(hgemm<0,false>, cudaFuncAttributeMaxDynamicSharedMemorySize, DSM);
    cudaFuncSetAttribute(hgemm<4,true >, cudaFuncAttributeMaxDynamicSharedMemorySize, DSM);
    cudaFuncSetAttribute(hgemm<2,false>, cudaFuncAttributeMaxDynamicSharedMemorySize, DSM);
    cudaFuncSetAttribute(hgemm<1,true >, cudaFuncAttributeMaxDynamicSharedMemorySize, DSM);
    cudaFuncSetAttribute(hgemm<3,false>, cudaFuncAttributeMaxDynamicSharedMemorySize, DSM);

    dim3 blk(128);
    dim3 tb(32, 8);
    const long long SD  = (long long)S_ * D_;
    const long long SS2 = (long long)S_ * S_;
    dim3 g1(D_ / 128, M_ / 128, 1);

    // launch order: index 3 = dense Q-projection GEMM (ncu profiles launch idx 3)
    ln_kernel<<<M_, 256>>>(x, ln1w, ln1b, h);                               // 0
    transpose_k<<<dim3(D_/32, D_/32), tb>>>(wq, wqT, D_, D_);               // 1
    transpose_k<<<dim3(D_/32, D_/32), tb>>>(wk, wkT, D_, D_);               // 2
    hgemm<0,true ><<<g1, blk, DSM>>>(h, D_, 0, 0, wqT, D_, 0, 0, q,  D_, 0, 0, D_, 1.f, 0, 0, 1);  // 3 <- profiled
    hgemm<0,true ><<<g1, blk, DSM>>>(h, D_, 0, 0, wkT, D_, 0, 0, k,  D_, 0, 0, D_, 1.f, 0, 0, 1);  // 4
    transpose_k<<<dim3(D_/32, D_/32), tb>>>(wv, wvT, D_, D_);               // 5
    hgemm<4,true ><<<g1, blk, DSM>>>(h, D_, 0, 0, wvT, D_, 0, 0, vt, S_, 0, 0, D_, 1.f, 0, 0, 1);  // 6

    // --- scores = Q K^T / sqrt(HD) (fp16 out) ---
    dim3 g2(S_ / 128, S_ / 128, B_ * H_);
    hgemm<0,true ><<<g2, blk, DSM>>>(q, D_, SD, HD_,
                                     k, D_, SD, HD_,
                                     sc, S_, (long long)H_ * SS2, SS2,
                                     HD_, 0.08838834764831845f, 0, 0, H_);

    // --- softmax: fp16 scores -> fp16 probs ---
    softmax_kernel<<<B_ * H_ * S_, 256>>>(sc, p);

    // --- O = P @ V  (B = V^T [HD, S] slices), fp16 out ---
    dim3 g3(HD_ / 128, S_ / 128, B_ * H_);
    hgemm<0,true ><<<g3, blk, DSM>>>(p, S_, (long long)H_ * SS2, SS2,
                                     vt, S_, (long long)D_ * S_, (long long)HD_ * S_,
                                     o,  D_, SD, HD_,
                                     S_, 1.f, 0, 0, H_);

    // --- out-projection + residual (fp32 residual stream) ---
    transpose_k<<<dim3(D_/32, D_/32), tb>>>(wo, woT, D_, D_);
    hgemm<2,false><<<g1, blk, DSM>>>(o, D_, 0, 0, woT, D_, 0, 0, x1, D_, 0, 0, D_, 1.f, 0, x, 1);

    // --- LN2 ---
    ln_kernel<<<M_, 256>>>(x1, ln2w, ln2b, h);

    // --- FC1 + bias + gelu (fp16 out) ---
    transpose_k<<<dim3(DFF_/32, D_/32), tb>>>(fc1w, fc1T, D_, DFF_);
    dim3 g4(DFF_ / 128, M_ / 128, 1);
    hgemm<1,true ><<<g4, blk, DSM>>>(h, D_, 0, 0, fc1T, D_, 0, 0, mid, DFF_, 0, 0, D_, 1.f, fc1b, 0, 1);

    // --- FC2 + bias + residual -> out (fp32) ---
    transpose_k<<<dim3(D_/32, DFF_/32), tb>>>(fc2w, fc2T, DFF_, D_);
    hgemm<3,false><<<g1, blk, DSM>>>(mid, DFF_, 0, 0, fc2T, DFF_, 0, 0, out, D_, 0, 0, DFF_, 1.f, fc2b, x1, 1);
}

// round 14
// speedup vs baseline: 1.4168x; 1.1025x over previous
#include <cuda_runtime.h>
#include <cuda_fp16.h>
#include <math.h>
#include <stdint.h>

#define B_   4
#define S_   2048
#define D_   2048
#define H_   16
#define HD_  128
#define DFF_ 8192
#define M_   (B_*S_)

// ---------------- scratch (static device globals; no allocation) ----------------
__device__ __half g_h   [(size_t)M_*D_];
__device__ __half g_qkv [(size_t)M_*3*D_];   // packed [M, 3D]: q | k | (v cols scattered)
__device__ __half g_vt  [(size_t)M_*D_];     // V^T: [b][d][s]
__device__ __half g_o   [(size_t)M_*D_];
__device__ float  g_x1  [(size_t)M_*D_];
__device__ __half g_mid [(size_t)M_*DFF_];
__device__ __half g_sc  [(size_t)B_*H_*S_*S_];   // fp16 attention scores
__device__ __half g_p   [(size_t)B_*H_*S_*S_];   // fp16 softmax probs
__device__ __half g_wqkvT[(size_t)3*D_*D_];  // [3D, D] transposed q|k|v weights
__device__ __half g_woT [(size_t)D_*D_];
__device__ __half g_fc1T[(size_t)DFF_*D_];   // [DFF, D]
__device__ __half g_fc2T[(size_t)D_*DFF_];   // [D, DFF]

__device__ __forceinline__ float gelu_new_f(float x) {
    const float c = 0.7978845608028654f;
    return 0.5f * x * (1.0f + tanhf(c * (x + 0.044715f * x * x * x)));
}

__device__ __forceinline__ uint32_t smem_u32(const void* p) {
    uint32_t a;
    asm("{ .reg .u64 t; cvta.to.shared.u64 t, %1; cvt.u32.u64 %0, t; }" : "=r"(a) : "l"(p));
    return a;
}

__device__ __forceinline__ void mma_fp16(float* d,
                                         uint32_t a0, uint32_t a1, uint32_t a2, uint32_t a3,
                                         uint32_t b0, uint32_t b1) {
    asm volatile("mma.sync.aligned.m16n8k16.row.col.f32.f16.f16.f32 "
                 "{%0,%1,%2,%3}, {%4,%5,%6,%7}, {%8,%9}, {%0,%1,%2,%3};"
                 : "+f"(d[0]), "+f"(d[1]), "+f"(d[2]), "+f"(d[3])
                 : "r"(a0), "r"(a1), "r"(a2), "r"(a3), "r"(b0), "r"(b1));
}

__device__ __forceinline__ void ldsm_x4(uint32_t& r0, uint32_t& r1, uint32_t& r2, uint32_t& r3,
                                        uint32_t addr) {
    asm volatile("ldmatrix.sync.aligned.m8n8.x4.shared.b16 {%0,%1,%2,%3}, [%4];"
                 : "=r"(r0), "=r"(r1), "=r"(r2), "=r"(r3) : "r"(addr));
}

#define CP_ASYNC16(dst_u32, src_ptr) \
    asm volatile("cp.async.cg.shared.global [%0], [%1], 16;" :: "r"(dst_u32), "l"(src_ptr))
#define CP_COMMIT() asm volatile("cp.async.commit_group;" ::: "memory")
#define CP_WAIT1()  asm volatile("cp.async.wait_group 1;" ::: "memory")
#define CP_WAIT0()  asm volatile("cp.async.wait_group 0;" ::: "memory")

// ---------------- LayerNorm: fp32 in -> fp16 out (feeds GEMMs only) ----------------
__global__ __launch_bounds__(256) void ln_kernel(const float* __restrict__ x,
                                                 const float* __restrict__ w,
                                                 const float* __restrict__ b,
                                                 __half* __restrict__ out) {
    __shared__ float redA[8], redB[8];
    size_t row = blockIdx.x;
    const float* xr = x + row * D_;
    __half2* orow = (__half2*)(out + row * D_);
    int t = threadIdx.x, lane = t & 31, wid = t >> 5;
    float v[8];
    float4 f0 = *(const float4*)(xr + t * 4);
    float4 f1 = *(const float4*)(xr + 1024 + t * 4);
    v[0]=f0.x; v[1]=f0.y; v[2]=f0.z; v[3]=f0.w;
    v[4]=f1.x; v[5]=f1.y; v[6]=f1.z; v[7]=f1.w;
    float s = 0.f;
    #pragma unroll
    for (int i = 0; i < 8; i++) s += v[i];
    #pragma unroll
    for (int o2 = 16; o2 > 0; o2 >>= 1) s += __shfl_xor_sync(0xffffffffu, s, o2);
    if (!lane) redA[wid] = s;
    __syncthreads();
    float tot = 0.f;
    #pragma unroll
    for (int i = 0; i < 8; i++) tot += redA[i];
    float mu = tot * (1.0f / (float)D_);
    float sq = 0.f;
    #pragma unroll
    for (int i = 0; i < 8; i++) { float d = v[i] - mu; sq += d * d; }
    #pragma unroll
    for (int o2 = 16; o2 > 0; o2 >>= 1) sq += __shfl_xor_sync(0xffffffffu, sq, o2);
    if (!lane) redB[wid] = sq;
    __syncthreads();
    float var = 0.f;
    #pragma unroll
    for (int i = 0; i < 8; i++) var += redB[i];
    var *= (1.0f / (float)D_);
    float inv = rsqrtf(var + 1e-5f);
    float4 w0 = *(const float4*)(w + t * 4);
    float4 w1 = *(const float4*)(w + 1024 + t * 4);
    float4 b0 = *(const float4*)(b + t * 4);
    float4 b1 = *(const float4*)(b + 1024 + t * 4);
    orow[t*2+0]   = __floats2half2_rn((v[0]-mu)*inv*w0.x + b0.x, (v[1]-mu)*inv*w0.y + b0.y);
    orow[t*2+1]   = __floats2half2_rn((v[2]-mu)*inv*w0.z + b0.z, (v[3]-mu)*inv*w0.w + b0.w);
    orow[512+t*2] = __floats2half2_rn((v[4]-mu)*inv*w1.x + b1.x, (v[5]-mu)*inv*w1.y + b1.y);
    orow[513+t*2] = __floats2half2_rn((v[6]-mu)*inv*w1.z + b1.z, (v[7]-mu)*inv*w1.w + b1.w);
}

// ---------------- softmax: fp16 scores in -> fp16 probs out ----------------
__global__ __launch_bounds__(256) void softmax_kernel(const __half* __restrict__ sc,
                                                      __half* __restrict__ pout) {
    __shared__ float redA[8], redB[8];
    const __half2* p = (const __half2*)(sc + (size_t)blockIdx.x * S_);
    __half2* po = (__half2*)(pout + (size_t)blockIdx.x * S_);
    int t = threadIdx.x, lane = t & 31, wid = t >> 5;
    float v[8];
    {
        __half2 h0 = p[t*2+0], h1 = p[t*2+1], h2 = p[512+t*2], h3 = p[513+t*2];
        float2 a = __half22float2(h0), b2 = __half22float2(h1);
        float2 c = __half22float2(h2), d2 = __half22float2(h3);
        v[0]=a.x; v[1]=a.y; v[2]=b2.x; v[3]=b2.y;
        v[4]=c.x; v[5]=c.y; v[6]=d2.x; v[7]=d2.y;
    }
    float mx = v[0];
    #pragma unroll
    for (int i = 1; i < 8; i++) mx = fmaxf(mx, v[i]);
    #pragma unroll
    for (int o2 = 16; o2 > 0; o2 >>= 1) mx = fmaxf(mx, __shfl_xor_sync(0xffffffffu, mx, o2));
    if (!lane) redA[wid] = mx;
    __syncthreads();
    float gmx = redA[0];
    #pragma unroll
    for (int i = 1; i < 8; i++) gmx = fmaxf(gmx, redA[i]);
    float s = 0.f;
    #pragma unroll
    for (int i = 0; i < 8; i++) { v[i] = __expf(v[i] - gmx); s += v[i]; }
    #pragma unroll
    for (int o2 = 16; o2 > 0; o2 >>= 1) s += __shfl_xor_sync(0xffffffffu, s, o2);
    if (!lane) redB[wid] = s;
    __syncthreads();
    float tot = 0.f;
    #pragma unroll
    for (int i = 0; i < 8; i++) tot += redB[i];
    float inv = 1.0f / tot;
    po[t*2+0]   = __floats2half2_rn(v[0]*inv, v[1]*inv);
    po[t*2+1]   = __floats2half2_rn(v[2]*inv, v[3]*inv);
    po[512+t*2] = __floats2half2_rn(v[4]*inv, v[5]*inv);
    po[513+t*2] = __floats2half2_rn(v[6]*inv, v[7]*inv);
}

// ---------------- transpose [R,C] fp32 -> [C,R] fp16 ----------------
__global__ __launch_bounds__(256) void transpose_k(const float* __restrict__ in,
                                                   __half* __restrict__ out, int R, int C) {
    __shared__ float t[32][33];
    int bx = blockIdx.x * 32, by = blockIdx.y * 32;
    int x = bx + threadIdx.x;
    #pragma unroll
    for (int i = 0; i < 32; i += 8)
        t[threadIdx.y + i][threadIdx.x] = in[(size_t)(by + threadIdx.y + i) * C + x];
    __syncthreads();
    int x2 = by + threadIdx.x;
    #pragma unroll
    for (int i = 0; i < 32; i += 8)
        out[(size_t)(bx + threadIdx.y + i) * R + x2] = __float2half_rn(t[threadIdx.x][threadIdx.y + i]);
}

// ---- 3-way transpose: z selects wq/wk/wv, dst packed at z*D*D in wqkvT ----
__global__ __launch_bounds__(256) void transpose3_k(const float* __restrict__ w0,
                                                    const float* __restrict__ w1,
                                                    const float* __restrict__ w2,
                                                    __half* __restrict__ out) {
    __shared__ float t[32][33];
    const float* in = (blockIdx.z == 0) ? w0 : (blockIdx.z == 1) ? w1 : w2;
    __half* dst = out + (size_t)blockIdx.z * D_ * D_;
    int bx = blockIdx.x * 32, by = blockIdx.y * 32;
    int x = bx + threadIdx.x;
    #pragma unroll
    for (int i = 0; i < 32; i += 8)
        t[threadIdx.y + i][threadIdx.x] = in[(size_t)(by + threadIdx.y + i) * D_ + x];
    __syncthreads();
    int x2 = by + threadIdx.x;
    #pragma unroll
    for (int i = 0; i < 32; i += 8)
        dst[(size_t)(bx + threadIdx.y + i) * D_ + x2] = __float2half_rn(t[threadIdx.x][threadIdx.y + i]);
}

// ---------------- fp16 mma.sync GEMM (R7-proven 2-stage config) ----------------
// CTA 128x128, K-tile 64 halves, 2-stage cp.async, 256 thr (8 warps 2x4, 64x32), 2 CTA/SM.
// EPI: 0=alpha*acc ; 1=gelu(acc+bias) ; 2=acc+resid ; 3=acc+bias+resid ;
//      5=merged qkv (n0 < 2D: half store to C; n0 >= 2D: V^T scatter via 'resid' ptr)
// OUTH: C is __half (else float)
#define W32 36
template<int EPI, bool OUTH>
__global__ __launch_bounds__(256, 2) void hgemm(
    const __half* __restrict__ A, int lda, long long sA1, long long sA2,
    const __half* __restrict__ Bm, int ldb, long long sB1, long long sB2,
    void* __restrict__ Cv, int ldc, long long sC1, long long sC2,
    int K, float alpha,
    const float* __restrict__ bias,
    const float* __restrict__ resid,
    int Hdiv)
{
    const int ASZ = 128 * W32;
    const int STG = 2 * ASZ;
    extern __shared__ uint32_t sm[];
    uint32_t* Abuf[2] = { sm,       sm + STG };
    uint32_t* Bbuf[2] = { sm + ASZ, sm + STG + ASZ };

    int z = blockIdx.z;
    int zb = z / Hdiv, zh = z % Hdiv;
    const __half* Ab = A  + (size_t)zb * sA1 + (size_t)zh * sA2;
    const __half* Bb = Bm + (size_t)zb * sB1 + (size_t)zh * sB2;

    int m0 = blockIdx.y * 128;
    int n0 = blockIdx.x * 128;
    int tid = threadIdx.x;
    int wid = tid >> 5, lane = tid & 31;
    int g = lane >> 2, tig = lane & 3;
    int warpM = wid >> 2, warpN = wid & 3;

    const __half* Abase = Ab + (size_t)m0 * lda;
    const __half* Bbase = Bb + (size_t)n0 * ldb;

    int aoff = ((warpM * 64 + (lane & 15)) * W32 + (lane >> 4) * 4) * 4;
    int boff = ((warpN * 32 + (lane >> 4) * 8 + (lane & 7)) * W32 + ((lane >> 3) & 1) * 4) * 4;

    float acc[4][4][4];
    #pragma unroll
    for (int i = 0; i < 4; i++)
        #pragma unroll
        for (int j = 0; j < 4; j++)
            #pragma unroll
            for (int r = 0; r < 4; r++) acc[i][j][r] = 0.f;

    int KT = K >> 6;

#define ISSUE_TILE(kt, bsel) do {                                              \
    const __half* Ag_ = Abase + (size_t)(kt) * 64;                             \
    const __half* Bg_ = Bbase + (size_t)(kt) * 64;                             \
    _Pragma("unroll")                                                          \
    for (int i_ = 0; i_ < 4; i_++) {                                           \
        int idx_ = i_ * 256 + tid;                                             \
        int row_ = idx_ >> 3, c8_ = idx_ & 7;                                  \
        uint32_t da_ = smem_u32(Abuf[bsel] + row_ * W32 + c8_ * 4);            \
        CP_ASYNC16(da_, Ag_ + (size_t)row_ * lda + c8_ * 8);                   \
    }                                                                          \
    _Pragma("unroll")                                                          \
    for (int i_ = 0; i_ < 4; i_++) {                                           \
        int idx_ = i_ * 256 + tid;                                             \
        int row_ = idx_ >> 3, c8_ = idx_ & 7;                                  \
        uint32_t db_ = smem_u32(Bbuf[bsel] + row_ * W32 + c8_ * 4);            \
        CP_ASYNC16(db_, Bg_ + (size_t)row_ * ldb + c8_ * 8);                   \
    }                                                                          \
    CP_COMMIT();                                                               \
} while (0)

    ISSUE_TILE(0, 0);

    for (int kt = 0; kt < KT; kt++) {
        int bsel = kt & 1;
        if (kt + 1 < KT) { ISSUE_TILE(kt + 1, bsel ^ 1); CP_WAIT1(); }
        else             { CP_WAIT0(); }
        __syncthreads();

        uint32_t As_base = smem_u32(Abuf[bsel]) + aoff;
        uint32_t Bs_base = smem_u32(Bbuf[bsel]) + boff;
        #pragma unroll
        for (int kk = 0; kk < 4; kk++) {
            uint32_t As_a = As_base + kk * 32;
            uint32_t Bs_a = Bs_base + kk * 32;
            uint32_t af[4][4];
            #pragma unroll
            for (int mt = 0; mt < 4; mt++)
                ldsm_x4(af[mt][0], af[mt][1], af[mt][2], af[mt][3],
                        As_a + mt * (16 * W32 * 4));
            uint32_t bf[4][2];
            ldsm_x4(bf[0][0], bf[0][1], bf[1][0], bf[1][1], Bs_a);
            ldsm_x4(bf[2][0], bf[2][1], bf[3][0], bf[3][1], Bs_a + 16 * W32 * 4);
            #pragma unroll
            for (int mt = 0; mt < 4; mt++)
                #pragma unroll
                for (int nt = 0; nt < 4; nt++)
                    mma_fp16(acc[mt][nt], af[mt][0], af[mt][1], af[mt][2], af[mt][3],
                             bf[nt][0], bf[nt][1]);
        }
        __syncthreads();
    }
#undef ISSUE_TILE

    float*  Cf = (float*)Cv  + (OUTH ? 0 : ((size_t)zb * sC1 + (size_t)zh * sC2));
    __half* Ch = (__half*)Cv + (OUTH ? ((size_t)zb * sC1 + (size_t)zh * sC2) : 0);
    __half* Vt = (__half*)resid;   // EPI==5 only
    #pragma unroll
    for (int mt = 0; mt < 4; mt++) {
        #pragma unroll
        for (int nt = 0; nt < 4; nt++) {
            int r0 = m0 + warpM * 64 + mt * 16 + g;
            int cN = n0 + warpN * 32 + nt * 8 + 2 * tig;
            #pragma unroll
            for (int hh = 0; hh < 2; hh++) {
                int rr = r0 + hh * 8;
                float e0 = acc[mt][nt][2 * hh + 0];
                float e1 = acc[mt][nt][2 * hh + 1];
                if (EPI == 0) { e0 *= alpha; e1 *= alpha; }
                if (EPI == 1 || EPI == 3) {
                    float2 bb = *(const float2*)(bias + cN);
                    e0 += bb.x; e1 += bb.y;
                }
                if (EPI == 1) { e0 = gelu_new_f(e0); e1 = gelu_new_f(e1); }
                if (EPI == 2 || EPI == 3) {
                    float2 rv = *(const float2*)(resid + (size_t)rr * ldc + cN);
                    e0 += rv.x; e1 += rv.y;
                }
                if (EPI == 5) {
                    if (n0 < 2 * D_) {
                        *(__half2*)(Ch + (size_t)rr * ldc + cN) = __floats2half2_rn(e0, e1);
                    } else {
                        int d = cN - 2 * D_;
                        int bidx = rr >> 11;            // rr / S_
                        int sloc = rr & (S_ - 1);
                        Vt[((size_t)bidx * D_ + d) * S_ + sloc]     = __float2half_rn(e0);
                        Vt[((size_t)bidx * D_ + d + 1) * S_ + sloc] = __float2half_rn(e1);
                    }
                } else if (OUTH) {
                    *(__half2*)(Ch + (size_t)rr * ldc + cN) = __floats2half2_rn(e0, e1);
                } else {
                    float2 st; st.x = e0; st.y = e1;
                    *(float2*)(Cf + (size_t)rr * ldc + cN) = st;
                }
            }
        }
    }
}

// ---------------- host ----------------
static const int DSM = 2 * 2 * 128 * W32 * 4;   // 73728 bytes

extern "C" void kernel_launch(void* const* d_in, const int* in_sizes, int n_in,
                              void* d_out, int out_size) {
    (void)in_sizes; (void)n_in; (void)out_size;
    const float* x    = (const float*)d_in[0];
    const float* wq   = (const float*)d_in[1];
    const float* wk   = (const float*)d_in[2];
    const float* wv   = (const float*)d_in[3];
    const float* wo   = (const float*)d_in[4];
    const float* ln1w = (const float*)d_in[5];
    const float* ln1b = (const float*)d_in[6];
    const float* ln2w = (const float*)d_in[7];
    const float* ln2b = (const float*)d_in[8];
    const float* fc1w = (const float*)d_in[9];
    const float* fc1b = (const float*)d_in[10];
    const float* fc2w = (const float*)d_in[11];
    const float* fc2b = (const float*)d_in[12];
    float* out = (float*)d_out;

    __half *h, *qkv, *vt, *o, *mid, *p, *sc;
    float *x1;
    __half *wqkvT, *woT, *fc1T, *fc2T;
    cudaGetSymbolAddress((void**)&h,     g_h);
    cudaGetSymbolAddress((void**)&qkv,   g_qkv);
    cudaGetSymbolAddress((void**)&vt,    g_vt);
    cudaGetSymbolAddress((void**)&o,     g_o);
    cudaGetSymbolAddress((void**)&x1,    g_x1);
    cudaGetSymbolAddress((void**)&mid,   g_mid);
    cudaGetSymbolAddress((void**)&sc,    g_sc);
    cudaGetSymbolAddress((void**)&p,     g_p);
    cudaGetSymbolAddress((void**)&wqkvT, g_wqkvT);
    cudaGetSymbolAddress((void**)&woT,   g_woT);
    cudaGetSymbolAddress((void**)&fc1T,  g_fc1T);
    cudaGetSymbolAddress((void**)&fc2T,  g_fc2T);

    cudaFuncSetAttribute(hgemm<5,true >, cudaFuncAttributeMaxDynamicSharedMemorySize, DSM);
    cudaFuncSetAttribute(hgemm<0,true >, cudaFuncAttributeMaxDynamicSharedMemorySize, DSM);
    cudaFuncSetAttribute(hgemm<2,false>, cudaFuncAttributeMaxDynamicSharedMemorySize, DSM);
    cudaFuncSetAttribute(hgemm<1,true >, cudaFuncAttributeMaxDynamicSharedMemorySize, DSM);
    cudaFuncSetAttribute(hgemm<3,false>, cudaFuncAttributeMaxDynamicSharedMemorySize, DSM);

    dim3 blk(256);
    dim3 tb(32, 8);
    const long long SD3 = (long long)S_ * 3 * D_;
    const long long SD  = (long long)S_ * D_;
    const long long SS2 = (long long)S_ * S_;

    // launch order: index 3 = merged QKV GEMM (ncu profiles launch idx 3)
    ln_kernel<<<M_, 256>>>(x, ln1w, ln1b, h);                               // 0
    transpose3_k<<<dim3(D_/32, D_/32, 3), tb>>>(wq, wk, wv, wqkvT);          // 1
    transpose_k<<<dim3(D_/32, D_/32), tb>>>(wo, woT, D_, D_);               // 2

    // --- merged QKV projection: [M,2048] @ [6144,2048]^T -> q|k packed + V^T scatter ---
    dim3 gqkv(3 * D_ / 128, M_ / 128, 1);
    hgemm<5,true ><<<gqkv, blk, DSM>>>(h, D_, 0, 0, wqkvT, D_, 0, 0,
                                       qkv, 3 * D_, 0, 0, D_, 1.f, 0, (const float*)vt, 1);  // 3

    // --- scores = Q K^T / sqrt(HD) (fp16 out); Q at col 0, K at col 2048 of qkv ---
    dim3 g2(S_ / 128, S_ / 128, B_ * H_);
    hgemm<0,true ><<<g2, blk, DSM>>>(qkv,      3 * D_, SD3, HD_,
                                     qkv + D_, 3 * D_, SD3, HD_,
                                     sc, S_, (long long)H_ * SS2, SS2,
                                     HD_, 0.08838834764831845f, 0, 0, H_);

    // --- softmax: fp16 scores -> fp16 probs ---
    softmax_kernel<<<B_ * H_ * S_, 256>>>(sc, p);

    // --- O = P @ V  (B = V^T [HD, S] slices), fp16 out ---
    dim3 g3(HD_ / 128, S_ / 128, B_ * H_);
    hgemm<0,true ><<<g3, blk, DSM>>>(p, S_, (long long)H_ * SS2, SS2,
                                     vt, S_, (long long)D_ * S_, (long long)HD_ * S_,
                                     o,  D_, SD, HD_,
                                     S_, 1.f, 0, 0, H_);

    // --- out-projection + residual (fp32 residual stream) ---
    dim3 g1(D_ / 128, M_ / 128, 1);
    hgemm<2,false><<<g1, blk, DSM>>>(o, D_, 0, 0, woT, D_, 0, 0, x1, D_, 0, 0, D_, 1.f, 0, x, 1);

    // --- LN2 ---
    ln_kernel<<<M_, 256>>>(x1, ln2w, ln2b, h);

    // --- FC1 + bias + gelu (fp16 out) ---
    transpose_k<<<dim3(DFF_/32, D_/32), tb>>>(fc1w, fc1T, D_, DFF_);
    dim3 g4(DFF_ / 128, M_ / 128, 1);
    hgemm<1,true ><<<g4, blk, DSM>>>(h, D_, 0, 0, fc1T, D_, 0, 0, mid, DFF_, 0, 0, D_, 1.f, fc1b, 0, 1);

    // --- FC2 + bias + residual -> out (fp32) ---
    transpose_k<<<dim3(D_/32, DFF_/32), tb>>>(fc2w, fc2T, DFF_, D_);
    hgemm<3,false><<<g1, blk, DSM>>>(mid, DFF_, 0, 0, fc2T, DFF_, 0, 0, out, D_, 0, 0, DFF_, 1.f, fc2b, x1, 1);
}

// round 15
// speedup vs baseline: 1.4287x; 1.0084x over previous
#include <cuda_runtime.h>
#include <cuda_fp16.h>
#include <math.h>
#include <stdint.h>

#define B_   4
#define S_   2048
#define D_   2048
#define H_   16
#define HD_  128
#define DFF_ 8192
#define M_   (B_*S_)

// ---------------- scratch (static device globals; no allocation) ----------------
__device__ __half g_h   [(size_t)M_*D_];
__device__ __half g_qkv [(size_t)M_*3*D_];   // packed [M, 3D]: q | k | (v cols scattered)
__device__ __half g_vt  [(size_t)M_*D_];     // V^T: [b][d][s]
__device__ __half g_o   [(size_t)M_*D_];
__device__ float  g_x1  [(size_t)M_*D_];
__device__ __half g_mid [(size_t)M_*DFF_];
__device__ __half g_sc  [(size_t)B_*H_*S_*S_];   // fp16 attention scores
__device__ __half g_p   [(size_t)B_*H_*S_*S_];   // fp16 softmax probs
__device__ __half g_wqkvT[(size_t)3*D_*D_];  // [3D, D] transposed q|k|v weights
__device__ __half g_woT [(size_t)D_*D_];
__device__ __half g_fc1T[(size_t)DFF_*D_];   // [DFF, D]
__device__ __half g_fc2T[(size_t)D_*DFF_];   // [D, DFF]

__device__ __forceinline__ float gelu_new_f(float x) {
    const float c = 0.7978845608028654f;
    return 0.5f * x * (1.0f + tanhf(c * (x + 0.044715f * x * x * x)));
}

__device__ __forceinline__ uint32_t smem_u32(const void* p) {
    uint32_t a;
    asm("{ .reg .u64 t; cvta.to.shared.u64 t, %1; cvt.u32.u64 %0, t; }" : "=r"(a) : "l"(p));
    return a;
}

__device__ __forceinline__ void mma_fp16(float* d,
                                         uint32_t a0, uint32_t a1, uint32_t a2, uint32_t a3,
                                         uint32_t b0, uint32_t b1) {
    asm volatile("mma.sync.aligned.m16n8k16.row.col.f32.f16.f16.f32 "
                 "{%0,%1,%2,%3}, {%4,%5,%6,%7}, {%8,%9}, {%0,%1,%2,%3};"
                 : "+f"(d[0]), "+f"(d[1]), "+f"(d[2]), "+f"(d[3])
                 : "r"(a0), "r"(a1), "r"(a2), "r"(a3), "r"(b0), "r"(b1));
}

__device__ __forceinline__ void ldsm_x4(uint32_t& r0, uint32_t& r1, uint32_t& r2, uint32_t& r3,
                                        uint32_t addr) {
    asm volatile("ldmatrix.sync.aligned.m8n8.x4.shared.b16 {%0,%1,%2,%3}, [%4];"
                 : "=r"(r0), "=r"(r1), "=r"(r2), "=r"(r3) : "r"(addr));
}

#define CP_ASYNC16(dst_u32, src_ptr) \
    asm volatile("cp.async.cg.shared.global [%0], [%1], 16;" :: "r"(dst_u32), "l"(src_ptr))
#define CP_COMMIT() asm volatile("cp.async.commit_group;" ::: "memory")
#define CP_WAIT1()  asm volatile("cp.async.wait_group 1;" ::: "memory")
#define CP_WAIT0()  asm volatile("cp.async.wait_group 0;" ::: "memory")

// ---------------- LayerNorm: fp32 in -> fp16 out (feeds GEMMs only) ----------------
__global__ __launch_bounds__(256) void ln_kernel(const float* __restrict__ x,
                                                 const float* __restrict__ w,
                                                 const float* __restrict__ b,
                                                 __half* __restrict__ out) {
    __shared__ float redA[8], redB[8];
    size_t row = blockIdx.x;
    const float* xr = x + row * D_;
    __half2* orow = (__half2*)(out + row * D_);
    int t = threadIdx.x, lane = t & 31, wid = t >> 5;
    float v[8];
    float4 f0 = *(const float4*)(xr + t * 4);
    float4 f1 = *(const float4*)(xr + 1024 + t * 4);
    v[0]=f0.x; v[1]=f0.y; v[2]=f0.z; v[3]=f0.w;
    v[4]=f1.x; v[5]=f1.y; v[6]=f1.z; v[7]=f1.w;
    float s = 0.f;
    #pragma unroll
    for (int i = 0; i < 8; i++) s += v[i];
    #pragma unroll
    for (int o2 = 16; o2 > 0; o2 >>= 1) s += __shfl_xor_sync(0xffffffffu, s, o2);
    if (!lane) redA[wid] = s;
    __syncthreads();
    float tot = 0.f;
    #pragma unroll
    for (int i = 0; i < 8; i++) tot += redA[i];
    float mu = tot * (1.0f / (float)D_);
    float sq = 0.f;
    #pragma unroll
    for (int i = 0; i < 8; i++) { float d = v[i] - mu; sq += d * d; }
    #pragma unroll
    for (int o2 = 16; o2 > 0; o2 >>= 1) sq += __shfl_xor_sync(0xffffffffu, sq, o2);
    if (!lane) redB[wid] = sq;
    __syncthreads();
    float var = 0.f;
    #pragma unroll
    for (int i = 0; i < 8; i++) var += redB[i];
    var *= (1.0f / (float)D_);
    float inv = rsqrtf(var + 1e-5f);
    float4 w0 = *(const float4*)(w + t * 4);
    float4 w1 = *(const float4*)(w + 1024 + t * 4);
    float4 b0 = *(const float4*)(b + t * 4);
    float4 b1 = *(const float4*)(b + 1024 + t * 4);
    orow[t*2+0]   = __floats2half2_rn((v[0]-mu)*inv*w0.x + b0.x, (v[1]-mu)*inv*w0.y + b0.y);
    orow[t*2+1]   = __floats2half2_rn((v[2]-mu)*inv*w0.z + b0.z, (v[3]-mu)*inv*w0.w + b0.w);
    orow[512+t*2] = __floats2half2_rn((v[4]-mu)*inv*w1.x + b1.x, (v[5]-mu)*inv*w1.y + b1.y);
    orow[513+t*2] = __floats2half2_rn((v[6]-mu)*inv*w1.z + b1.z, (v[7]-mu)*inv*w1.w + b1.w);
}

// ---------------- softmax: fp16 scores in -> fp16 probs out ----------------
__global__ __launch_bounds__(256) void softmax_kernel(const __half* __restrict__ sc,
                                                      __half* __restrict__ pout) {
    __shared__ float redA[8], redB[8];
    const __half2* p = (const __half2*)(sc + (size_t)blockIdx.x * S_);
    __half2* po = (__half2*)(pout + (size_t)blockIdx.x * S_);
    int t = threadIdx.x, lane = t & 31, wid = t >> 5;
    float v[8];
    {
        __half2 h0 = p[t*2+0], h1 = p[t*2+1], h2 = p[512+t*2], h3 = p[513+t*2];
        float2 a = __half22float2(h0), b2 = __half22float2(h1);
        float2 c = __half22float2(h2), d2 = __half22float2(h3);
        v[0]=a.x; v[1]=a.y; v[2]=b2.x; v[3]=b2.y;
        v[4]=c.x; v[5]=c.y; v[6]=d2.x; v[7]=d2.y;
    }
    float mx = v[0];
    #pragma unroll
    for (int i = 1; i < 8; i++) mx = fmaxf(mx, v[i]);
    #pragma unroll
    for (int o2 = 16; o2 > 0; o2 >>= 1) mx = fmaxf(mx, __shfl_xor_sync(0xffffffffu, mx, o2));
    if (!lane) redA[wid] = mx;
    __syncthreads();
    float gmx = redA[0];
    #pragma unroll
    for (int i = 1; i < 8; i++) gmx = fmaxf(gmx, redA[i]);
    float s = 0.f;
    #pragma unroll
    for (int i = 0; i < 8; i++) { v[i] = __expf(v[i] - gmx); s += v[i]; }
    #pragma unroll
    for (int o2 = 16; o2 > 0; o2 >>= 1) s += __shfl_xor_sync(0xffffffffu, s, o2);
    if (!lane) redB[wid] = s;
    __syncthreads();
    float tot = 0.f;
    #pragma unroll
    for (int i = 0; i < 8; i++) tot += redB[i];
    float inv = 1.0f / tot;
    po[t*2+0]   = __floats2half2_rn(v[0]*inv, v[1]*inv);
    po[t*2+1]   = __floats2half2_rn(v[2]*inv, v[3]*inv);
    po[512+t*2] = __floats2half2_rn(v[4]*inv, v[5]*inv);
    po[513+t*2] = __floats2half2_rn(v[6]*inv, v[7]*inv);
}

// ---------------- transpose [R,C] fp32 -> [C,R] fp16 ----------------
__global__ __launch_bounds__(256) void transpose_k(const float* __restrict__ in,
                                                   __half* __restrict__ out, int R, int C) {
    __shared__ float t[32][33];
    int bx = blockIdx.x * 32, by = blockIdx.y * 32;
    int x = bx + threadIdx.x;
    #pragma unroll
    for (int i = 0; i < 32; i += 8)
        t[threadIdx.y + i][threadIdx.x] = in[(size_t)(by + threadIdx.y + i) * C + x];
    __syncthreads();
    int x2 = by + threadIdx.x;
    #pragma unroll
    for (int i = 0; i < 32; i += 8)
        out[(size_t)(bx + threadIdx.y + i) * R + x2] = __float2half_rn(t[threadIdx.x][threadIdx.y + i]);
}

// ---- 3-way transpose: z selects wq/wk/wv, dst packed at z*D*D in wqkvT ----
__global__ __launch_bounds__(256) void transpose3_k(const float* __restrict__ w0,
                                                    const float* __restrict__ w1,
                                                    const float* __restrict__ w2,
                                                    __half* __restrict__ out) {
    __shared__ float t[32][33];
    const float* in = (blockIdx.z == 0) ? w0 : (blockIdx.z == 1) ? w1 : w2;
    __half* dst = out + (size_t)blockIdx.z * D_ * D_;
    int bx = blockIdx.x * 32, by = blockIdx.y * 32;
    int x = bx + threadIdx.x;
    #pragma unroll
    for (int i = 0; i < 32; i += 8)
        t[threadIdx.y + i][threadIdx.x] = in[(size_t)(by + threadIdx.y + i) * D_ + x];
    __syncthreads();
    int x2 = by + threadIdx.x;
    #pragma unroll
    for (int i = 0; i < 32; i += 8)
        dst[(size_t)(bx + threadIdx.y + i) * D_ + x2] = __float2half_rn(t[threadIdx.x][threadIdx.y + i]);
}

// ---------------- one-shot K=128 GEMM (score GEMM): C = alpha * A @ B^T, fp16 out ----
// Whole K-slab loaded once (A,B: 128 rows x 128 halves, QR=68 padded), one sync,
// 8 uninterrupted k16 steps. 2 CTA/SM. Batched over (b,h) via blockIdx.z.
#define QR 68   // u32 row stride for 128-half rows
__global__ __launch_bounds__(256, 2) void hgemm_k128(
    const __half* __restrict__ A, int lda, long long sA1, long long sA2,
    const __half* __restrict__ Bm, int ldb, long long sB1, long long sB2,
    __half* __restrict__ C, int ldc, long long sC1, long long sC2,
    float alpha, int Hdiv)
{
    extern __shared__ uint32_t sk[];
    uint32_t* As = sk;               // 128*68 u32
    uint32_t* Bs = sk + 128 * QR;

    int z = blockIdx.z;
    int zb = z / Hdiv, zh = z % Hdiv;
    const __half* Ab = A  + (size_t)zb * sA1 + (size_t)zh * sA2 + (size_t)(blockIdx.y * 128) * lda;
    const __half* Bb = Bm + (size_t)zb * sB1 + (size_t)zh * sB2 + (size_t)(blockIdx.x * 128) * ldb;
    __half*       Cb = C  + (size_t)zb * sC1 + (size_t)zh * sC2;

    int tid = threadIdx.x;
    int wid = tid >> 5, lane = tid & 31;
    int g = lane >> 2, tig = lane & 3;
    int warpM = wid >> 2, warpN = wid & 3;     // 2 x 4, warp tile 64x32

    // load both 32KB slabs: 2048 float4 each, 8 per thread
    #pragma unroll
    for (int i = 0; i < 8; i++) {
        int idx = i * 256 + tid;
        int row = idx >> 4, c16 = idx & 15;
        CP_ASYNC16(smem_u32(As + row * QR + c16 * 4), Ab + (size_t)row * lda + c16 * 8);
    }
    #pragma unroll
    for (int i = 0; i < 8; i++) {
        int idx = i * 256 + tid;
        int row = idx >> 4, c16 = idx & 15;
        CP_ASYNC16(smem_u32(Bs + row * QR + c16 * 4), Bb + (size_t)row * ldb + c16 * 8);
    }
    CP_COMMIT();

    uint32_t Aaddr = smem_u32(As) + ((warpM * 64 + (lane & 15)) * QR + (lane >> 4) * 4) * 4;
    uint32_t Baddr = smem_u32(Bs) + ((warpN * 32 + (lane >> 4) * 8 + (lane & 7)) * QR + ((lane >> 3) & 1) * 4) * 4;

    float acc[4][4][4];
    #pragma unroll
    for (int i = 0; i < 4; i++)
        #pragma unroll
        for (int j = 0; j < 4; j++)
            #pragma unroll
            for (int r = 0; r < 4; r++) acc[i][j][r] = 0.f;

    CP_WAIT0();
    __syncthreads();

    #pragma unroll
    for (int kk = 0; kk < 8; kk++) {
        uint32_t af[4][4];
        #pragma unroll
        for (int mt = 0; mt < 4; mt++)
            ldsm_x4(af[mt][0], af[mt][1], af[mt][2], af[mt][3],
                    Aaddr + mt * (16 * QR * 4) + kk * 32);
        uint32_t bf[4][2];
        ldsm_x4(bf[0][0], bf[0][1], bf[1][0], bf[1][1], Baddr + kk * 32);
        ldsm_x4(bf[2][0], bf[2][1], bf[3][0], bf[3][1], Baddr + 16 * QR * 4 + kk * 32);
        #pragma unroll
        for (int mt = 0; mt < 4; mt++)
            #pragma unroll
            for (int nt = 0; nt < 4; nt++)
                mma_fp16(acc[mt][nt], af[mt][0], af[mt][1], af[mt][2], af[mt][3],
                         bf[nt][0], bf[nt][1]);
    }

    #pragma unroll
    for (int mt = 0; mt < 4; mt++) {
        #pragma unroll
        for (int nt = 0; nt < 4; nt++) {
            int r0 = blockIdx.y * 128 + warpM * 64 + mt * 16 + g;
            int cN = blockIdx.x * 128 + warpN * 32 + nt * 8 + 2 * tig;
            #pragma unroll
            for (int hh = 0; hh < 2; hh++) {
                int rr = r0 + hh * 8;
                float e0 = acc[mt][nt][2 * hh + 0] * alpha;
                float e1 = acc[mt][nt][2 * hh + 1] * alpha;
                *(__half2*)(Cb + (size_t)rr * ldc + cN) = __floats2half2_rn(e0, e1);
            }
        }
    }
}

// ---------------- fp16 mma.sync GEMM (R7-proven 2-stage config) ----------------
// EPI: 0=alpha*acc ; 1=gelu(acc+bias) ; 2=acc+resid ; 3=acc+bias+resid ;
//      5=merged qkv (n0 < 2D: half store to C; n0 >= 2D: V^T scatter via 'resid' ptr)
#define W32 36
template<int EPI, bool OUTH>
__global__ __launch_bounds__(256, 2) void hgemm(
    const __half* __restrict__ A, int lda, long long sA1, long long sA2,
    const __half* __restrict__ Bm, int ldb, long long sB1, long long sB2,
    void* __restrict__ Cv, int ldc, long long sC1, long long sC2,
    int K, float alpha,
    const float* __restrict__ bias,
    const float* __restrict__ resid,
    int Hdiv)
{
    const int ASZ = 128 * W32;
    const int STG = 2 * ASZ;
    extern __shared__ uint32_t sm[];
    uint32_t* Abuf[2] = { sm,       sm + STG };
    uint32_t* Bbuf[2] = { sm + ASZ, sm + STG + ASZ };

    int z = blockIdx.z;
    int zb = z / Hdiv, zh = z % Hdiv;
    const __half* Ab = A  + (size_t)zb * sA1 + (size_t)zh * sA2;
    const __half* Bb = Bm + (size_t)zb * sB1 + (size_t)zh * sB2;

    int m0 = blockIdx.y * 128;
    int n0 = blockIdx.x * 128;
    int tid = threadIdx.x;
    int wid = tid >> 5, lane = tid & 31;
    int g = lane >> 2, tig = lane & 3;
    int warpM = wid >> 2, warpN = wid & 3;

    const __half* Abase = Ab + (size_t)m0 * lda;
    const __half* Bbase = Bb + (size_t)n0 * ldb;

    int aoff = ((warpM * 64 + (lane & 15)) * W32 + (lane >> 4) * 4) * 4;
    int boff = ((warpN * 32 + (lane >> 4) * 8 + (lane & 7)) * W32 + ((lane >> 3) & 1) * 4) * 4;

    float acc[4][4][4];
    #pragma unroll
    for (int i = 0; i < 4; i++)
        #pragma unroll
        for (int j = 0; j < 4; j++)
            #pragma unroll
            for (int r = 0; r < 4; r++) acc[i][j][r] = 0.f;

    int KT = K >> 6;

#define ISSUE_TILE(kt, bsel) do {                                              \
    const __half* Ag_ = Abase + (size_t)(kt) * 64;                             \
    const __half* Bg_ = Bbase + (size_t)(kt) * 64;                             \
    _Pragma("unroll")                                                          \
    for (int i_ = 0; i_ < 4; i_++) {                                           \
        int idx_ = i_ * 256 + tid;                                             \
        int row_ = idx_ >> 3, c8_ = idx_ & 7;                                  \
        uint32_t da_ = smem_u32(Abuf[bsel] + row_ * W32 + c8_ * 4);            \
        CP_ASYNC16(da_, Ag_ + (size_t)row_ * lda + c8_ * 8);                   \
    }                                                                          \
    _Pragma("unroll")                                                          \
    for (int i_ = 0; i_ < 4; i_++) {                                           \
        int idx_ = i_ * 256 + tid;                                             \
        int row_ = idx_ >> 3, c8_ = idx_ & 7;                                  \
        uint32_t db_ = smem_u32(Bbuf[bsel] + row_ * W32 + c8_ * 4);            \
        CP_ASYNC16(db_, Bg_ + (size_t)row_ * ldb + c8_ * 8);                   \
    }                                                                          \
    CP_COMMIT();                                                               \
} while (0)

    ISSUE_TILE(0, 0);

    for (int kt = 0; kt < KT; kt++) {
        int bsel = kt & 1;
        if (kt + 1 < KT) { ISSUE_TILE(kt + 1, bsel ^ 1); CP_WAIT1(); }
        else             { CP_WAIT0(); }
        __syncthreads();

        uint32_t As_base = smem_u32(Abuf[bsel]) + aoff;
        uint32_t Bs_base = smem_u32(Bbuf[bsel]) + boff;
        #pragma unroll
        for (int kk = 0; kk < 4; kk++) {
            uint32_t As_a = As_base + kk * 32;
            uint32_t Bs_a = Bs_base + kk * 32;
            uint32_t af[4][4];
            #pragma unroll
            for (int mt = 0; mt < 4; mt++)
                ldsm_x4(af[mt][0], af[mt][1], af[mt][2], af[mt][3],
                        As_a + mt * (16 * W32 * 4));
            uint32_t bf[4][2];
            ldsm_x4(bf[0][0], bf[0][1], bf[1][0], bf[1][1], Bs_a);
            ldsm_x4(bf[2][0], bf[2][1], bf[3][0], bf[3][1], Bs_a + 16 * W32 * 4);
            #pragma unroll
            for (int mt = 0; mt < 4; mt++)
                #pragma unroll
                for (int nt = 0; nt < 4; nt++)
                    mma_fp16(acc[mt][nt], af[mt][0], af[mt][1], af[mt][2], af[mt][3],
                             bf[nt][0], bf[nt][1]);
        }
        __syncthreads();
    }
#undef ISSUE_TILE

    float*  Cf = (float*)Cv  + (OUTH ? 0 : ((size_t)zb * sC1 + (size_t)zh * sC2));
    __half* Ch = (__half*)Cv + (OUTH ? ((size_t)zb * sC1 + (size_t)zh * sC2) : 0);
    __half* Vt = (__half*)resid;   // EPI==5 only
    #pragma unroll
    for (int mt = 0; mt < 4; mt++) {
        #pragma unroll
        for (int nt = 0; nt < 4; nt++) {
            int r0 = m0 + warpM * 64 + mt * 16 + g;
            int cN = n0 + warpN * 32 + nt * 8 + 2 * tig;
            #pragma unroll
            for (int hh = 0; hh < 2; hh++) {
                int rr = r0 + hh * 8;
                float e0 = acc[mt][nt][2 * hh + 0];
                float e1 = acc[mt][nt][2 * hh + 1];
                if (EPI == 0) { e0 *= alpha; e1 *= alpha; }
                if (EPI == 1 || EPI == 3) {
                    float2 bb = *(const float2*)(bias + cN);
                    e0 += bb.x; e1 += bb.y;
                }
                if (EPI == 1) { e0 = gelu_new_f(e0); e1 = gelu_new_f(e1); }
                if (EPI == 2 || EPI == 3) {
                    float2 rv = *(const float2*)(resid + (size_t)rr * ldc + cN);
                    e0 += rv.x; e1 += rv.y;
                }
                if (EPI == 5) {
                    if (n0 < 2 * D_) {
                        *(__half2*)(Ch + (size_t)rr * ldc + cN) = __floats2half2_rn(e0, e1);
                    } else {
                        int d = cN - 2 * D_;
                        int bidx = rr >> 11;            // rr / S_
                        int sloc = rr & (S_ - 1);
                        Vt[((size_t)bidx * D_ + d) * S_ + sloc]     = __float2half_rn(e0);
                        Vt[((size_t)bidx * D_ + d + 1) * S_ + sloc] = __float2half_rn(e1);
                    }
                } else if (OUTH) {
                    *(__half2*)(Ch + (size_t)rr * ldc + cN) = __floats2half2_rn(e0, e1);
                } else {
                    float2 st; st.x = e0; st.y = e1;
                    *(float2*)(Cf + (size_t)rr * ldc + cN) = st;
                }
            }
        }
    }
}

// ---------------- host ----------------
static const int DSM  = 2 * 2 * 128 * W32 * 4;   // 73728 bytes (hgemm)
static const int KDSM = 2 * 128 * QR * 4;        // 69632 bytes (hgemm_k128)

extern "C" void kernel_launch(void* const* d_in, const int* in_sizes, int n_in,
                              void* d_out, int out_size) {
    (void)in_sizes; (void)n_in; (void)out_size;
    const float* x    = (const float*)d_in[0];
    const float* wq   = (const float*)d_in[1];
    const float* wk   = (const float*)d_in[2];
    const float* wv   = (const float*)d_in[3];
    const float* wo   = (const float*)d_in[4];
    const float* ln1w = (const float*)d_in[5];
    const float* ln1b = (const float*)d_in[6];
    const float* ln2w = (const float*)d_in[7];
    const float* ln2b = (const float*)d_in[8];
    const float* fc1w = (const float*)d_in[9];
    const float* fc1b = (const float*)d_in[10];
    const float* fc2w = (const float*)d_in[11];
    const float* fc2b = (const float*)d_in[12];
    float* out = (float*)d_out;

    __half *h, *qkv, *vt, *o, *mid, *p, *sc;
    float *x1;
    __half *wqkvT, *woT, *fc1T, *fc2T;
    cudaGetSymbolAddress((void**)&h,     g_h);
    cudaGetSymbolAddress((void**)&qkv,   g_qkv);
    cudaGetSymbolAddress((void**)&vt,    g_vt);
    cudaGetSymbolAddress((void**)&o,     g_o);
    cudaGetSymbolAddress((void**)&x1,    g_x1);
    cudaGetSymbolAddress((void**)&mid,   g_mid);
    cudaGetSymbolAddress((void**)&sc,    g_sc);
    cudaGetSymbolAddress((void**)&p,     g_p);
    cudaGetSymbolAddress((void**)&wqkvT, g_wqkvT);
    cudaGetSymbolAddress((void**)&woT,   g_woT);
    cudaGetSymbolAddress((void**)&fc1T,  g_fc1T);
    cudaGetSymbolAddress((void**)&fc2T,  g_fc2T);

    cudaFuncSetAttribute(hgemm<5,true >, cudaFuncAttributeMaxDynamicSharedMemorySize, DSM);
    cudaFuncSetAttribute(hgemm<0,true >, cudaFuncAttributeMaxDynamicSharedMemorySize, DSM);
    cudaFuncSetAttribute(hgemm<2,false>, cudaFuncAttributeMaxDynamicSharedMemorySize, DSM);
    cudaFuncSetAttribute(hgemm<1,true >, cudaFuncAttributeMaxDynamicSharedMemorySize, DSM);
    cudaFuncSetAttribute(hgemm<3,false>, cudaFuncAttributeMaxDynamicSharedMemorySize, DSM);
    cudaFuncSetAttribute(hgemm_k128,     cudaFuncAttributeMaxDynamicSharedMemorySize, KDSM);

    dim3 blk(256);
    dim3 tb(32, 8);
    const long long SD3 = (long long)S_ * 3 * D_;
    const long long SD  = (long long)S_ * D_;
    const long long SS2 = (long long)S_ * S_;

    // launch order: index 3 = merged QKV GEMM (ncu profiles launch idx 3)
    ln_kernel<<<M_, 256>>>(x, ln1w, ln1b, h);                               // 0
    transpose3_k<<<dim3(D_/32, D_/32, 3), tb>>>(wq, wk, wv, wqkvT);          // 1
    transpose_k<<<dim3(D_/32, D_/32), tb>>>(wo, woT, D_, D_);               // 2

    // --- merged QKV projection: [M,2048] @ [6144,2048]^T -> q|k packed + V^T scatter ---
    dim3 gqkv(3 * D_ / 128, M_ / 128, 1);
    hgemm<5,true ><<<gqkv, blk, DSM>>>(h, D_, 0, 0, wqkvT, D_, 0, 0,
                                       qkv, 3 * D_, 0, 0, D_, 1.f, 0, (const float*)vt, 1);  // 3

    // --- scores = Q K^T / sqrt(HD) (fp16 out), one-shot K=128 kernel ---
    dim3 g2(S_ / 128, S_ / 128, B_ * H_);
    hgemm_k128<<<g2, blk, KDSM>>>(qkv,      3 * D_, SD3, HD_,
                                  qkv + D_, 3 * D_, SD3, HD_,
                                  sc, S_, (long long)H_ * SS2, SS2,
                                  0.08838834764831845f, H_);

    // --- softmax: fp16 scores -> fp16 probs ---
    softmax_kernel<<<B_ * H_ * S_, 256>>>(sc, p);

    // --- O = P @ V  (B = V^T [HD, S] slices), fp16 out ---
    dim3 g3(HD_ / 128, S_ / 128, B_ * H_);
    hgemm<0,true ><<<g3, blk, DSM>>>(p, S_, (long long)H_ * SS2, SS2,
                                     vt, S_, (long long)D_ * S_, (long long)HD_ * S_,
                                     o,  D_, SD, HD_,
                                     S_, 1.f, 0, 0, H_);

    // --- out-projection + residual (fp32 residual stream) ---
    dim3 g1(D_ / 128, M_ / 128, 1);
    hgemm<2,false><<<g1, blk, DSM>>>(o, D_, 0, 0, woT, D_, 0, 0, x1, D_, 0, 0, D_, 1.f, 0, x, 1);

    // --- LN2 ---
    ln_kernel<<<M_, 256>>>(x1, ln2w, ln2b, h);

    // --- FC1 + bias + gelu (fp16 out) ---
    transpose_k<<<dim3(DFF_/32, D_/32), tb>>>(fc1w, fc1T, D_, DFF_);
    dim3 g4(DFF_ / 128, M_ / 128, 1);
    hgemm<1,true ><<<g4, blk, DSM>>>(h, D_, 0, 0, fc1T, D_, 0, 0, mid, DFF_, 0, 0, D_, 1.f, fc1b, 0, 1);

    // --- FC2 + bias + residual -> out (fp32) ---
    transpose_k<<<dim3(D_/32, DFF_/32), tb>>>(fc2w, fc2T, DFF_, D_);
    hgemm<3,false><<<g1, blk, DSM>>>(mid, DFF_, 0, 0, fc2T, DFF_, 0, 0, out, D_, 0, 0, DFF_, 1.f, fc2b, x1, 1);
}

// round 16
// speedup vs baseline: 1.4599x; 1.0218x over previous
#include <cuda_runtime.h>
#include <cuda_fp16.h>
#include <math.h>
#include <stdint.h>

#define B_   4
#define S_   2048
#define D_   2048
#define H_   16
#define HD_  128
#define DFF_ 8192
#define M_   (B_*S_)

// ---------------- scratch (static device globals; no allocation) ----------------
__device__ __half g_h   [(size_t)M_*D_];
__device__ __half g_qkv [(size_t)M_*3*D_];   // packed [M, 3D]: q | k | (v cols scattered)
__device__ __half g_vt  [(size_t)M_*D_];     // V^T: [b][d][s]
__device__ __half g_o   [(size_t)M_*D_];
__device__ float  g_x1  [(size_t)M_*D_];
__device__ __half g_mid [(size_t)M_*DFF_];
__device__ __half g_sc  [(size_t)B_*H_*S_*S_];   // fp16 attention scores
__device__ __half g_p   [(size_t)B_*H_*S_*S_];   // fp16 softmax probs
__device__ __half g_wqkvT[(size_t)3*D_*D_];  // [3D, D] transposed q|k|v weights
__device__ __half g_woT [(size_t)D_*D_];
__device__ __half g_fc1T[(size_t)DFF_*D_];   // [DFF, D]
__device__ __half g_fc2T[(size_t)D_*DFF_];   // [D, DFF]

__device__ __forceinline__ float gelu_new_f(float x) {
    const float c = 0.7978845608028654f;
    return 0.5f * x * (1.0f + tanhf(c * (x + 0.044715f * x * x * x)));
}

__device__ __forceinline__ uint32_t smem_u32(const void* p) {
    uint32_t a;
    asm("{ .reg .u64 t; cvta.to.shared.u64 t, %1; cvt.u32.u64 %0, t; }" : "=r"(a) : "l"(p));
    return a;
}

__device__ __forceinline__ void mma_fp16(float* d,
                                         uint32_t a0, uint32_t a1, uint32_t a2, uint32_t a3,
                                         uint32_t b0, uint32_t b1) {
    asm volatile("mma.sync.aligned.m16n8k16.row.col.f32.f16.f16.f32 "
                 "{%0,%1,%2,%3}, {%4,%5,%6,%7}, {%8,%9}, {%0,%1,%2,%3};"
                 : "+f"(d[0]), "+f"(d[1]), "+f"(d[2]), "+f"(d[3])
                 : "r"(a0), "r"(a1), "r"(a2), "r"(a3), "r"(b0), "r"(b1));
}

__device__ __forceinline__ void ldsm_x4(uint32_t& r0, uint32_t& r1, uint32_t& r2, uint32_t& r3,
                                        uint32_t addr) {
    asm volatile("ldmatrix.sync.aligned.m8n8.x4.shared.b16 {%0,%1,%2,%3}, [%4];"
                 : "=r"(r0), "=r"(r1), "=r"(r2), "=r"(r3) : "r"(addr));
}

#define CP_ASYNC16(dst_u32, src_ptr) \
    asm volatile("cp.async.cg.shared.global [%0], [%1], 16;" :: "r"(dst_u32), "l"(src_ptr))
#define CP_COMMIT() asm volatile("cp.async.commit_group;" ::: "memory")
#define CP_WAIT0()  asm volatile("cp.async.wait_group 0;" ::: "memory")

// ---------------- LayerNorm: fp32 in -> fp16 out (feeds GEMMs only) ----------------
__global__ __launch_bounds__(256) void ln_kernel(const float* __restrict__ x,
                                                 const float* __restrict__ w,
                                                 const float* __restrict__ b,
                                                 __half* __restrict__ out) {
    __shared__ float redA[8], redB[8];
    size_t row = blockIdx.x;
    const float* xr = x + row * D_;
    __half2* orow = (__half2*)(out + row * D_);
    int t = threadIdx.x, lane = t & 31, wid = t >> 5;
    float v[8];
    float4 f0 = *(const float4*)(xr + t * 4);
    float4 f1 = *(const float4*)(xr + 1024 + t * 4);
    v[0]=f0.x; v[1]=f0.y; v[2]=f0.z; v[3]=f0.w;
    v[4]=f1.x; v[5]=f1.y; v[6]=f1.z; v[7]=f1.w;
    float s = 0.f;
    #pragma unroll
    for (int i = 0; i < 8; i++) s += v[i];
    #pragma unroll
    for (int o2 = 16; o2 > 0; o2 >>= 1) s += __shfl_xor_sync(0xffffffffu, s, o2);
    if (!lane) redA[wid] = s;
    __syncthreads();
    float tot = 0.f;
    #pragma unroll
    for (int i = 0; i < 8; i++) tot += redA[i];
    float mu = tot * (1.0f / (float)D_);
    float sq = 0.f;
    #pragma unroll
    for (int i = 0; i < 8; i++) { float d = v[i] - mu; sq += d * d; }
    #pragma unroll
    for (int o2 = 16; o2 > 0; o2 >>= 1) sq += __shfl_xor_sync(0xffffffffu, sq, o2);
    if (!lane) redB[wid] = sq;
    __syncthreads();
    float var = 0.f;
    #pragma unroll
    for (int i = 0; i < 8; i++) var += redB[i];
    var *= (1.0f / (float)D_);
    float inv = rsqrtf(var + 1e-5f);
    float4 w0 = *(const float4*)(w + t * 4);
    float4 w1 = *(const float4*)(w + 1024 + t * 4);
    float4 b0 = *(const float4*)(b + t * 4);
    float4 b1 = *(const float4*)(b + 1024 + t * 4);
    orow[t*2+0]   = __floats2half2_rn((v[0]-mu)*inv*w0.x + b0.x, (v[1]-mu)*inv*w0.y + b0.y);
    orow[t*2+1]   = __floats2half2_rn((v[2]-mu)*inv*w0.z + b0.z, (v[3]-mu)*inv*w0.w + b0.w);
    orow[512+t*2] = __floats2half2_rn((v[4]-mu)*inv*w1.x + b1.x, (v[5]-mu)*inv*w1.y + b1.y);
    orow[513+t*2] = __floats2half2_rn((v[6]-mu)*inv*w1.z + b1.z, (v[7]-mu)*inv*w1.w + b1.w);
}

// ---------------- softmax: fp16 scores in -> fp16 probs out ----------------
__global__ __launch_bounds__(256) void softmax_kernel(const __half* __restrict__ sc,
                                                      __half* __restrict__ pout) {
    __shared__ float redA[8], redB[8];
    const __half2* p = (const __half2*)(sc + (size_t)blockIdx.x * S_);
    __half2* po = (__half2*)(pout + (size_t)blockIdx.x * S_);
    int t = threadIdx.x, lane = t & 31, wid = t >> 5;
    float v[8];
    {
        __half2 h0 = p[t*2+0], h1 = p[t*2+1], h2 = p[512+t*2], h3 = p[513+t*2];
        float2 a = __half22float2(h0), b2 = __half22float2(h1);
        float2 c = __half22float2(h2), d2 = __half22float2(h3);
        v[0]=a.x; v[1]=a.y; v[2]=b2.x; v[3]=b2.y;
        v[4]=c.x; v[5]=c.y; v[6]=d2.x; v[7]=d2.y;
    }
    float mx = v[0];
    #pragma unroll
    for (int i = 1; i < 8; i++) mx = fmaxf(mx, v[i]);
    #pragma unroll
    for (int o2 = 16; o2 > 0; o2 >>= 1) mx = fmaxf(mx, __shfl_xor_sync(0xffffffffu, mx, o2));
    if (!lane) redA[wid] = mx;
    __syncthreads();
    float gmx = redA[0];
    #pragma unroll
    for (int i = 1; i < 8; i++) gmx = fmaxf(gmx, redA[i]);
    float s = 0.f;
    #pragma unroll
    for (int i = 0; i < 8; i++) { v[i] = __expf(v[i] - gmx); s += v[i]; }
    #pragma unroll
    for (int o2 = 16; o2 > 0; o2 >>= 1) s += __shfl_xor_sync(0xffffffffu, s, o2);
    if (!lane) redB[wid] = s;
    __syncthreads();
    float tot = 0.f;
    #pragma unroll
    for (int i = 0; i < 8; i++) tot += redB[i];
    float inv = 1.0f / tot;
    po[t*2+0]   = __floats2half2_rn(v[0]*inv, v[1]*inv);
    po[t*2+1]   = __floats2half2_rn(v[2]*inv, v[3]*inv);
    po[512+t*2] = __floats2half2_rn(v[4]*inv, v[5]*inv);
    po[513+t*2] = __floats2half2_rn(v[6]*inv, v[7]*inv);
}

// ---------------- transpose [R,C] fp32 -> [C,R] fp16 ----------------
__global__ __launch_bounds__(256) void transpose_k(const float* __restrict__ in,
                                                   __half* __restrict__ out, int R, int C) {
    __shared__ float t[32][33];
    int bx = blockIdx.x * 32, by = blockIdx.y * 32;
    int x = bx + threadIdx.x;
    #pragma unroll
    for (int i = 0; i < 32; i += 8)
        t[threadIdx.y + i][threadIdx.x] = in[(size_t)(by + threadIdx.y + i) * C + x];
    __syncthreads();
    int x2 = by + threadIdx.x;
    #pragma unroll
    for (int i = 0; i < 32; i += 8)
        out[(size_t)(bx + threadIdx.y + i) * R + x2] = __float2half_rn(t[threadIdx.x][threadIdx.y + i]);
}

// ---- 3-way transpose: z selects wq/wk/wv, dst packed at z*D*D in wqkvT ----
__global__ __launch_bounds__(256) void transpose3_k(const float* __restrict__ w0,
                                                    const float* __restrict__ w1,
                                                    const float* __restrict__ w2,
                                                    __half* __restrict__ out) {
    __shared__ float t[32][33];
    const float* in = (blockIdx.z == 0) ? w0 : (blockIdx.z == 1) ? w1 : w2;
    __half* dst = out + (size_t)blockIdx.z * D_ * D_;
    int bx = blockIdx.x * 32, by = blockIdx.y * 32;
    int x = bx + threadIdx.x;
    #pragma unroll
    for (int i = 0; i < 32; i += 8)
        t[threadIdx.y + i][threadIdx.x] = in[(size_t)(by + threadIdx.y + i) * D_ + x];
    __syncthreads();
    int x2 = by + threadIdx.x;
    #pragma unroll
    for (int i = 0; i < 32; i += 8)
        dst[(size_t)(bx + threadIdx.y + i) * D_ + x2] = __float2half_rn(t[threadIdx.x][threadIdx.y + i]);
}

// ---------------- one-shot K=128 GEMM (score GEMM): C = alpha * A @ B^T, fp16 out ----
#define QR 68   // u32 row stride for 128-half rows
__global__ __launch_bounds__(256, 2) void hgemm_k128(
    const __half* __restrict__ A, int lda, long long sA1, long long sA2,
    const __half* __restrict__ Bm, int ldb, long long sB1, long long sB2,
    __half* __restrict__ C, int ldc, long long sC1, long long sC2,
    float alpha, int Hdiv)
{
    extern __shared__ uint32_t sk[];
    uint32_t* As = sk;               // 128*68 u32
    uint32_t* Bs = sk + 128 * QR;

    int z = blockIdx.z;
    int zb = z / Hdiv, zh = z % Hdiv;
    const __half* Ab = A  + (size_t)zb * sA1 + (size_t)zh * sA2 + (size_t)(blockIdx.y * 128) * lda;
    const __half* Bb = Bm + (size_t)zb * sB1 + (size_t)zh * sB2 + (size_t)(blockIdx.x * 128) * ldb;
    __half*       Cb = C  + (size_t)zb * sC1 + (size_t)zh * sC2;

    int tid = threadIdx.x;
    int wid = tid >> 5, lane = tid & 31;
    int g = lane >> 2, tig = lane & 3;
    int warpM = wid >> 2, warpN = wid & 3;     // 2 x 4, warp tile 64x32

    #pragma unroll
    for (int i = 0; i < 8; i++) {
        int idx = i * 256 + tid;
        int row = idx >> 4, c16 = idx & 15;
        CP_ASYNC16(smem_u32(As + row * QR + c16 * 4), Ab + (size_t)row * lda + c16 * 8);
    }
    #pragma unroll
    for (int i = 0; i < 8; i++) {
        int idx = i * 256 + tid;
        int row = idx >> 4, c16 = idx & 15;
        CP_ASYNC16(smem_u32(Bs + row * QR + c16 * 4), Bb + (size_t)row * ldb + c16 * 8);
    }
    CP_COMMIT();

    uint32_t Aaddr = smem_u32(As) + ((warpM * 64 + (lane & 15)) * QR + (lane >> 4) * 4) * 4;
    uint32_t Baddr = smem_u32(Bs) + ((warpN * 32 + (lane >> 4) * 8 + (lane & 7)) * QR + ((lane >> 3) & 1) * 4) * 4;

    float acc[4][4][4];
    #pragma unroll
    for (int i = 0; i < 4; i++)
        #pragma unroll
        for (int j = 0; j < 4; j++)
            #pragma unroll
            for (int r = 0; r < 4; r++) acc[i][j][r] = 0.f;

    CP_WAIT0();
    __syncthreads();

    #pragma unroll
    for (int kk = 0; kk < 8; kk++) {
        uint32_t af[4][4];
        #pragma unroll
        for (int mt = 0; mt < 4; mt++)
            ldsm_x4(af[mt][0], af[mt][1], af[mt][2], af[mt][3],
                    Aaddr + mt * (16 * QR * 4) + kk * 32);
        uint32_t bf[4][2];
        ldsm_x4(bf[0][0], bf[0][1], bf[1][0], bf[1][1], Baddr + kk * 32);
        ldsm_x4(bf[2][0], bf[2][1], bf[3][0], bf[3][1], Baddr + 16 * QR * 4 + kk * 32);
        #pragma unroll
        for (int mt = 0; mt < 4; mt++)
            #pragma unroll
            for (int nt = 0; nt < 4; nt++)
                mma_fp16(acc[mt][nt], af[mt][0], af[mt][1], af[mt][2], af[mt][3],
                         bf[nt][0], bf[nt][1]);
    }

    #pragma unroll
    for (int mt = 0; mt < 4; mt++) {
        #pragma unroll
        for (int nt = 0; nt < 4; nt++) {
            int r0 = blockIdx.y * 128 + warpM * 64 + mt * 16 + g;
            int cN = blockIdx.x * 128 + warpN * 32 + nt * 8 + 2 * tig;
            #pragma unroll
            for (int hh = 0; hh < 2; hh++) {
                int rr = r0 + hh * 8;
                float e0 = acc[mt][nt][2 * hh + 0] * alpha;
                float e1 = acc[mt][nt][2 * hh + 1] * alpha;
                *(__half2*)(Cb + (size_t)rr * ldc + cN) = __floats2half2_rn(e0, e1);
            }
        }
    }
}

// ---------------- fp16 mma.sync GEMM (2-stage, SINGLE sync per k-tile) ----------------
// loop kt: WAIT0 -> sync -> ISSUE(kt+1) -> compute(kt).
// The leading sync both publishes tile kt to all warps AND proves all warps finished
// reading buf[(kt+1)%2] (computed in kt-1), so ISSUE can overwrite it barrier-free.
// EPI: 0=alpha*acc ; 1=gelu(acc+bias) ; 2=acc+resid ; 3=acc+bias+resid ;
//      5=merged qkv (n0 < 2D: half store to C; n0 >= 2D: V^T scatter via 'resid' ptr)
#define W32 36
template<int EPI, bool OUTH>
__global__ __launch_bounds__(256, 2) void hgemm(
    const __half* __restrict__ A, int lda, long long sA1, long long sA2,
    const __half* __restrict__ Bm, int ldb, long long sB1, long long sB2,
    void* __restrict__ Cv, int ldc, long long sC1, long long sC2,
    int K, float alpha,
    const float* __restrict__ bias,
    const float* __restrict__ resid,
    int Hdiv)
{
    const int ASZ = 128 * W32;
    const int STG = 2 * ASZ;
    extern __shared__ uint32_t sm[];
    uint32_t* Abuf[2] = { sm,       sm + STG };
    uint32_t* Bbuf[2] = { sm + ASZ, sm + STG + ASZ };

    int z = blockIdx.z;
    int zb = z / Hdiv, zh = z % Hdiv;
    const __half* Ab = A  + (size_t)zb * sA1 + (size_t)zh * sA2;
    const __half* Bb = Bm + (size_t)zb * sB1 + (size_t)zh * sB2;

    int m0 = blockIdx.y * 128;
    int n0 = blockIdx.x * 128;
    int tid = threadIdx.x;
    int wid = tid >> 5, lane = tid & 31;
    int g = lane >> 2, tig = lane & 3;
    int warpM = wid >> 2, warpN = wid & 3;

    const __half* Abase = Ab + (size_t)m0 * lda;
    const __half* Bbase = Bb + (size_t)n0 * ldb;

    int aoff = ((warpM * 64 + (lane & 15)) * W32 + (lane >> 4) * 4) * 4;
    int boff = ((warpN * 32 + (lane >> 4) * 8 + (lane & 7)) * W32 + ((lane >> 3) & 1) * 4) * 4;

    float acc[4][4][4];
    #pragma unroll
    for (int i = 0; i < 4; i++)
        #pragma unroll
        for (int j = 0; j < 4; j++)
            #pragma unroll
            for (int r = 0; r < 4; r++) acc[i][j][r] = 0.f;

    int KT = K >> 6;

#define ISSUE_TILE(kt, bsel) do {                                              \
    const __half* Ag_ = Abase + (size_t)(kt) * 64;                             \
    const __half* Bg_ = Bbase + (size_t)(kt) * 64;                             \
    _Pragma("unroll")                                                          \
    for (int i_ = 0; i_ < 4; i_++) {                                           \
        int idx_ = i_ * 256 + tid;                                             \
        int row_ = idx_ >> 3, c8_ = idx_ & 7;                                  \
        uint32_t da_ = smem_u32(Abuf[bsel] + row_ * W32 + c8_ * 4);            \
        CP_ASYNC16(da_, Ag_ + (size_t)row_ * lda + c8_ * 8);                   \
    }                                                                          \
    _Pragma("unroll")                                                          \
    for (int i_ = 0; i_ < 4; i_++) {                                           \
        int idx_ = i_ * 256 + tid;                                             \
        int row_ = idx_ >> 3, c8_ = idx_ & 7;                                  \
        uint32_t db_ = smem_u32(Bbuf[bsel] + row_ * W32 + c8_ * 4);            \
        CP_ASYNC16(db_, Bg_ + (size_t)row_ * ldb + c8_ * 8);                   \
    }                                                                          \
    CP_COMMIT();                                                               \
} while (0)

    ISSUE_TILE(0, 0);

    for (int kt = 0; kt < KT; kt++) {
        int bsel = kt & 1;
        CP_WAIT0();          // tile kt arrived (only group outstanding)
        __syncthreads();     // publish tile kt; proves buf[bsel^1] readers done
        if (kt + 1 < KT) ISSUE_TILE(kt + 1, bsel ^ 1);

        uint32_t As_base = smem_u32(Abuf[bsel]) + aoff;
        uint32_t Bs_base = smem_u32(Bbuf[bsel]) + boff;
        #pragma unroll
        for (int kk = 0; kk < 4; kk++) {
            uint32_t As_a = As_base + kk * 32;
            uint32_t Bs_a = Bs_base + kk * 32;
            uint32_t af[4][4];
            #pragma unroll
            for (int mt = 0; mt < 4; mt++)
                ldsm_x4(af[mt][0], af[mt][1], af[mt][2], af[mt][3],
                        As_a + mt * (16 * W32 * 4));
            uint32_t bf[4][2];
            ldsm_x4(bf[0][0], bf[0][1], bf[1][0], bf[1][1], Bs_a);
            ldsm_x4(bf[2][0], bf[2][1], bf[3][0], bf[3][1], Bs_a + 16 * W32 * 4);
            #pragma unroll
            for (int mt = 0; mt < 4; mt++)
                #pragma unroll
                for (int nt = 0; nt < 4; nt++)
                    mma_fp16(acc[mt][nt], af[mt][0], af[mt][1], af[mt][2], af[mt][3],
                             bf[nt][0], bf[nt][1]);
        }
    }
#undef ISSUE_TILE

    float*  Cf = (float*)Cv  + (OUTH ? 0 : ((size_t)zb * sC1 + (size_t)zh * sC2));
    __half* Ch = (__half*)Cv + (OUTH ? ((size_t)zb * sC1 + (size_t)zh * sC2) : 0);
    __half* Vt = (__half*)resid;   // EPI==5 only
    #pragma unroll
    for (int mt = 0; mt < 4; mt++) {
        #pragma unroll
        for (int nt = 0; nt < 4; nt++) {
            int r0 = m0 + warpM * 64 + mt * 16 + g;
            int cN = n0 + warpN * 32 + nt * 8 + 2 * tig;
            #pragma unroll
            for (int hh = 0; hh < 2; hh++) {
                int rr = r0 + hh * 8;
                float e0 = acc[mt][nt][2 * hh + 0];
                float e1 = acc[mt][nt][2 * hh + 1];
                if (EPI == 0) { e0 *= alpha; e1 *= alpha; }
                if (EPI == 1 || EPI == 3) {
                    float2 bb = *(const float2*)(bias + cN);
                    e0 += bb.x; e1 += bb.y;
                }
                if (EPI == 1) { e0 = gelu_new_f(e0); e1 = gelu_new_f(e1); }
                if (EPI == 2 || EPI == 3) {
                    float2 rv = *(const float2*)(resid + (size_t)rr * ldc + cN);
                    e0 += rv.x; e1 += rv.y;
                }
                if (EPI == 5) {
                    if (n0 < 2 * D_) {
                        *(__half2*)(Ch + (size_t)rr * ldc + cN) = __floats2half2_rn(e0, e1);
                    } else {
                        int d = cN - 2 * D_;
                        int bidx = rr >> 11;            // rr / S_
                        int sloc = rr & (S_ - 1);
                        Vt[((size_t)bidx * D_ + d) * S_ + sloc]     = __float2half_rn(e0);
                        Vt[((size_t)bidx * D_ + d + 1) * S_ + sloc] = __float2half_rn(e1);
                    }
                } else if (OUTH) {
                    *(__half2*)(Ch + (size_t)rr * ldc + cN) = __floats2half2_rn(e0, e1);
                } else {
                    float2 st; st.x = e0; st.y = e1;
                    *(float2*)(Cf + (size_t)rr * ldc + cN) = st;
                }
            }
        }
    }
}

// ---------------- host ----------------
static const int DSM  = 2 * 2 * 128 * W32 * 4;   // 73728 bytes (hgemm)
static const int KDSM = 2 * 128 * QR * 4;        // 69632 bytes (hgemm_k128)

extern "C" void kernel_launch(void* const* d_in, const int* in_sizes, int n_in,
                              void* d_out, int out_size) {
    (void)in_sizes; (void)n_in; (void)out_size;
    const float* x    = (const float*)d_in[0];
    const float* wq   = (const float*)d_in[1];
    const float* wk   = (const float*)d_in[2];
    const float* wv   = (const float*)d_in[3];
    const float* wo   = (const float*)d_in[4];
    const float* ln1w = (const float*)d_in[5];
    const float* ln1b = (const float*)d_in[6];
    const float* ln2w = (const float*)d_in[7];
    const float* ln2b = (const float*)d_in[8];
    const float* fc1w = (const float*)d_in[9];
    const float* fc1b = (const float*)d_in[10];
    const float* fc2w = (const float*)d_in[11];
    const float* fc2b = (const float*)d_in[12];
    float* out = (float*)d_out;

    __half *h, *qkv, *vt, *o, *mid, *p, *sc;
    float *x1;
    __half *wqkvT, *woT, *fc1T, *fc2T;
    cudaGetSymbolAddress((void**)&h,     g_h);
    cudaGetSymbolAddress((void**)&qkv,   g_qkv);
    cudaGetSymbolAddress((void**)&vt,    g_vt);
    cudaGetSymbolAddress((void**)&o,     g_o);
    cudaGetSymbolAddress((void**)&x1,    g_x1);
    cudaGetSymbolAddress((void**)&mid,   g_mid);
    cudaGetSymbolAddress((void**)&sc,    g_sc);
    cudaGetSymbolAddress((void**)&p,     g_p);
    cudaGetSymbolAddress((void**)&wqkvT, g_wqkvT);
    cudaGetSymbolAddress((void**)&woT,   g_woT);
    cudaGetSymbolAddress((void**)&fc1T,  g_fc1T);
    cudaGetSymbolAddress((void**)&fc2T,  g_fc2T);

    cudaFuncSetAttribute(hgemm<5,true >, cudaFuncAttributeMaxDynamicSharedMemorySize, DSM);
    cudaFuncSetAttribute(hgemm<0,true >, cudaFuncAttributeMaxDynamicSharedMemorySize, DSM);
    cudaFuncSetAttribute(hgemm<2,false>, cudaFuncAttributeMaxDynamicSharedMemorySize, DSM);
    cudaFuncSetAttribute(hgemm<1,true >, cudaFuncAttributeMaxDynamicSharedMemorySize, DSM);
    cudaFuncSetAttribute(hgemm<3,false>, cudaFuncAttributeMaxDynamicSharedMemorySize, DSM);
    cudaFuncSetAttribute(hgemm_k128,     cudaFuncAttributeMaxDynamicSharedMemorySize, KDSM);

    dim3 blk(256);
    dim3 tb(32, 8);
    const long long SD3 = (long long)S_ * 3 * D_;
    const long long SD  = (long long)S_ * D_;
    const long long SS2 = (long long)S_ * S_;

    // launch order: index 3 = merged QKV GEMM (ncu profiles launch idx 3)
    ln_kernel<<<M_, 256>>>(x, ln1w, ln1b, h);                               // 0
    transpose3_k<<<dim3(D_/32, D_/32, 3), tb>>>(wq, wk, wv, wqkvT);          // 1
    transpose_k<<<dim3(D_/32, D_/32), tb>>>(wo, woT, D_, D_);               // 2

    // --- merged QKV projection: [M,2048] @ [6144,2048]^T -> q|k packed + V^T scatter ---
    dim3 gqkv(3 * D_ / 128, M_ / 128, 1);
    hgemm<5,true ><<<gqkv, blk, DSM>>>(h, D_, 0, 0, wqkvT, D_, 0, 0,
                                       qkv, 3 * D_, 0, 0, D_, 1.f, 0, (const float*)vt, 1);  // 3

    // --- scores = Q K^T / sqrt(HD) (fp16 out), one-shot K=128 kernel ---
    dim3 g2(S_ / 128, S_ / 128, B_ * H_);
    hgemm_k128<<<g2, blk, KDSM>>>(qkv,      3 * D_, SD3, HD_,
                                  qkv + D_, 3 * D_, SD3, HD_,
                                  sc, S_, (long long)H_ * SS2, SS2,
                                  0.08838834764831845f, H_);

    // --- softmax: fp16 scores -> fp16 probs ---
    softmax_kernel<<<B_ * H_ * S_, 256>>>(sc, p);

    // --- O = P @ V  (B = V^T [HD, S] slices), fp16 out ---
    dim3 g3(HD_ / 128, S_ / 128, B_ * H_);
    hgemm<0,true ><<<g3, blk, DSM>>>(p, S_, (long long)H_ * SS2, SS2,
                                     vt, S_, (long long)D_ * S_, (long long)HD_ * S_,
                                     o,  D_, SD, HD_,
                                     S_, 1.f, 0, 0, H_);

    // --- out-projection + residual (fp32 residual stream) ---
    dim3 g1(D_ / 128, M_ / 128, 1);
    hgemm<2,false><<<g1, blk, DSM>>>(o, D_, 0, 0, woT, D_, 0, 0, x1, D_, 0, 0, D_, 1.f, 0, x, 1);

    // --- LN2 ---
    ln_kernel<<<M_, 256>>>(x1, ln2w, ln2b, h);

    // --- FC1 + bias + gelu (fp16 out) ---
    transpose_k<<<dim3(DFF_/32, D_/32), tb>>>(fc1w, fc1T, D_, DFF_);
    dim3 g4(DFF_ / 128, M_ / 128, 1);
    hgemm<1,true ><<<g4, blk, DSM>>>(h, D_, 0, 0, fc1T, D_, 0, 0, mid, DFF_, 0, 0, D_, 1.f, fc1b, 0, 1);

    // --- FC2 + bias + residual -> out (fp32) ---
    transpose_k<<<dim3(D_/32, DFF_/32), tb>>>(fc2w, fc2T, DFF_, D_);
    hgemm<3,false><<<g1, blk, DSM>>>(mid, DFF_, 0, 0, fc2T, DFF_, 0, 0, out, D_, 0, 0, DFF_, 1.f, fc2b, x1, 1);
}

// round 17
// speedup vs baseline: 1.4814x; 1.0148x over previous
#include <cuda_runtime.h>
#include <cuda_fp16.h>
#include <math.h>
#include <stdint.h>

#define B_   4
#define S_   2048
#define D_   2048
#define H_   16
#define HD_  128
#define DFF_ 8192
#define M_   (B_*S_)

// ---------------- scratch (static device globals; no allocation) ----------------
__device__ __half g_h   [(size_t)M_*D_];
__device__ __half g_qkv [(size_t)M_*3*D_];   // packed [M, 3D]: q | k | (v cols scattered)
__device__ __half g_vt  [(size_t)M_*D_];     // V^T: [b][d][s]
__device__ __half g_o   [(size_t)M_*D_];
__device__ float  g_x1  [(size_t)M_*D_];
__device__ __half g_mid [(size_t)M_*DFF_];
__device__ __half g_sc  [(size_t)B_*H_*S_*S_];   // fp16 attention scores
__device__ __half g_p   [(size_t)B_*H_*S_*S_];   // fp16 softmax probs
__device__ __half g_wqkvT[(size_t)3*D_*D_];  // [3D, D] transposed q|k|v weights
__device__ __half g_woT [(size_t)D_*D_];
__device__ __half g_fc1T[(size_t)DFF_*D_];   // [DFF, D]
__device__ __half g_fc2T[(size_t)D_*DFF_];   // [D, DFF]

__device__ __forceinline__ float gelu_new_f(float x) {
    const float c = 0.7978845608028654f;
    return 0.5f * x * (1.0f + tanhf(c * (x + 0.044715f * x * x * x)));
}

__device__ __forceinline__ uint32_t smem_u32(const void* p) {
    uint32_t a;
    asm("{ .reg .u64 t; cvta.to.shared.u64 t, %1; cvt.u32.u64 %0, t; }" : "=r"(a) : "l"(p));
    return a;
}

__device__ __forceinline__ void mma_fp16(float* d,
                                         uint32_t a0, uint32_t a1, uint32_t a2, uint32_t a3,
                                         uint32_t b0, uint32_t b1) {
    asm volatile("mma.sync.aligned.m16n8k16.row.col.f32.f16.f16.f32 "
                 "{%0,%1,%2,%3}, {%4,%5,%6,%7}, {%8,%9}, {%0,%1,%2,%3};"
                 : "+f"(d[0]), "+f"(d[1]), "+f"(d[2]), "+f"(d[3])
                 : "r"(a0), "r"(a1), "r"(a2), "r"(a3), "r"(b0), "r"(b1));
}

__device__ __forceinline__ void ldsm_x4(uint32_t& r0, uint32_t& r1, uint32_t& r2, uint32_t& r3,
                                        uint32_t addr) {
    asm volatile("ldmatrix.sync.aligned.m8n8.x4.shared.b16 {%0,%1,%2,%3}, [%4];"
                 : "=r"(r0), "=r"(r1), "=r"(r2), "=r"(r3) : "r"(addr));
}

#define CP_ASYNC16(dst_u32, src_ptr) \
    asm volatile("cp.async.cg.shared.global [%0], [%1], 16;" :: "r"(dst_u32), "l"(src_ptr))
#define CP_COMMIT() asm volatile("cp.async.commit_group;" ::: "memory")
#define CP_WAIT0()  asm volatile("cp.async.wait_group 0;" ::: "memory")

// ---------------- LayerNorm: fp32 in -> fp16 out (feeds GEMMs only) ----------------
__global__ __launch_bounds__(256) void ln_kernel(const float* __restrict__ x,
                                                 const float* __restrict__ w,
                                                 const float* __restrict__ b,
                                                 __half* __restrict__ out) {
    __shared__ float redA[8], redB[8];
    size_t row = blockIdx.x;
    const float* xr = x + row * D_;
    __half2* orow = (__half2*)(out + row * D_);
    int t = threadIdx.x, lane = t & 31, wid = t >> 5;
    float v[8];
    float4 f0 = *(const float4*)(xr + t * 4);
    float4 f1 = *(const float4*)(xr + 1024 + t * 4);
    v[0]=f0.x; v[1]=f0.y; v[2]=f0.z; v[3]=f0.w;
    v[4]=f1.x; v[5]=f1.y; v[6]=f1.z; v[7]=f1.w;
    float s = 0.f;
    #pragma unroll
    for (int i = 0; i < 8; i++) s += v[i];
    #pragma unroll
    for (int o2 = 16; o2 > 0; o2 >>= 1) s += __shfl_xor_sync(0xffffffffu, s, o2);
    if (!lane) redA[wid] = s;
    __syncthreads();
    float tot = 0.f;
    #pragma unroll
    for (int i = 0; i < 8; i++) tot += redA[i];
    float mu = tot * (1.0f / (float)D_);
    float sq = 0.f;
    #pragma unroll
    for (int i = 0; i < 8; i++) { float d = v[i] - mu; sq += d * d; }
    #pragma unroll
    for (int o2 = 16; o2 > 0; o2 >>= 1) sq += __shfl_xor_sync(0xffffffffu, sq, o2);
    if (!lane) redB[wid] = sq;
    __syncthreads();
    float var = 0.f;
    #pragma unroll
    for (int i = 0; i < 8; i++) var += redB[i];
    var *= (1.0f / (float)D_);
    float inv = rsqrtf(var + 1e-5f);
    float4 w0 = *(const float4*)(w + t * 4);
    float4 w1 = *(const float4*)(w + 1024 + t * 4);
    float4 b0 = *(const float4*)(b + t * 4);
    float4 b1 = *(const float4*)(b + 1024 + t * 4);
    orow[t*2+0]   = __floats2half2_rn((v[0]-mu)*inv*w0.x + b0.x, (v[1]-mu)*inv*w0.y + b0.y);
    orow[t*2+1]   = __floats2half2_rn((v[2]-mu)*inv*w0.z + b0.z, (v[3]-mu)*inv*w0.w + b0.w);
    orow[512+t*2] = __floats2half2_rn((v[4]-mu)*inv*w1.x + b1.x, (v[5]-mu)*inv*w1.y + b1.y);
    orow[513+t*2] = __floats2half2_rn((v[6]-mu)*inv*w1.z + b1.z, (v[7]-mu)*inv*w1.w + b1.w);
}

// ---------------- warp-per-row softmax: fp16 in -> fp16 out ----------------
// 256 thr = 8 warps = 8 rows per block. Lane owns 64 halves (8 x uint4).
// Pure register + shuffle reductions; no smem, no block barriers.
__global__ __launch_bounds__(256) void softmax_kernel(const __half* __restrict__ sc,
                                                      __half* __restrict__ pout) {
    int row = blockIdx.x * 8 + (threadIdx.x >> 5);
    int lane = threadIdx.x & 31;
    const uint4* src = (const uint4*)(sc + (size_t)row * S_);
    uint4* dst = (uint4*)(pout + (size_t)row * S_);
    const uint32_t FULL = 0xffffffffu;

    uint4 d[8];
    #pragma unroll
    for (int i = 0; i < 8; i++) d[i] = src[i * 32 + lane];

    float f[64];
    #pragma unroll
    for (int i = 0; i < 8; i++) {
        const __half2* hp = (const __half2*)&d[i];
        #pragma unroll
        for (int j = 0; j < 4; j++) {
            float2 fv = __half22float2(hp[j]);
            f[i * 8 + j * 2]     = fv.x;
            f[i * 8 + j * 2 + 1] = fv.y;
        }
    }

    float mx = f[0];
    #pragma unroll
    for (int i = 1; i < 64; i++) mx = fmaxf(mx, f[i]);
    #pragma unroll
    for (int o2 = 16; o2 > 0; o2 >>= 1) mx = fmaxf(mx, __shfl_xor_sync(FULL, mx, o2));

    float s = 0.f;
    #pragma unroll
    for (int i = 0; i < 64; i++) { f[i] = __expf(f[i] - mx); s += f[i]; }
    #pragma unroll
    for (int o2 = 16; o2 > 0; o2 >>= 1) s += __shfl_xor_sync(FULL, s, o2);
    float inv = 1.0f / s;

    #pragma unroll
    for (int i = 0; i < 8; i++) {
        __half2* hp = (__half2*)&d[i];
        #pragma unroll
        for (int j = 0; j < 4; j++)
            hp[j] = __floats2half2_rn(f[i * 8 + j * 2] * inv, f[i * 8 + j * 2 + 1] * inv);
        dst[i * 32 + lane] = d[i];
    }
}

// ---------------- transpose [R,C] fp32 -> [C,R] fp16 ----------------
__global__ __launch_bounds__(256) void transpose_k(const float* __restrict__ in,
                                                   __half* __restrict__ out, int R, int C) {
    __shared__ float t[32][33];
    int bx = blockIdx.x * 32, by = blockIdx.y * 32;
    int x = bx + threadIdx.x;
    #pragma unroll
    for (int i = 0; i < 32; i += 8)
        t[threadIdx.y + i][threadIdx.x] = in[(size_t)(by + threadIdx.y + i) * C + x];
    __syncthreads();
    int x2 = by + threadIdx.x;
    #pragma unroll
    for (int i = 0; i < 32; i += 8)
        out[(size_t)(bx + threadIdx.y + i) * R + x2] = __float2half_rn(t[threadIdx.x][threadIdx.y + i]);
}

// ---- 3-way transpose: z selects wq/wk/wv, dst packed at z*D*D in wqkvT ----
__global__ __launch_bounds__(256) void transpose3_k(const float* __restrict__ w0,
                                                    const float* __restrict__ w1,
                                                    const float* __restrict__ w2,
                                                    __half* __restrict__ out) {
    __shared__ float t[32][33];
    const float* in = (blockIdx.z == 0) ? w0 : (blockIdx.z == 1) ? w1 : w2;
    __half* dst = out + (size_t)blockIdx.z * D_ * D_;
    int bx = blockIdx.x * 32, by = blockIdx.y * 32;
    int x = bx + threadIdx.x;
    #pragma unroll
    for (int i = 0; i < 32; i += 8)
        t[threadIdx.y + i][threadIdx.x] = in[(size_t)(by + threadIdx.y + i) * D_ + x];
    __syncthreads();
    int x2 = by + threadIdx.x;
    #pragma unroll
    for (int i = 0; i < 32; i += 8)
        dst[(size_t)(bx + threadIdx.y + i) * D_ + x2] = __float2half_rn(t[threadIdx.x][threadIdx.y + i]);
}

// ---------------- one-shot K=128 GEMM (score GEMM): C = alpha * A @ B^T, fp16 out ----
#define QR 68   // u32 row stride for 128-half rows
__global__ __launch_bounds__(256, 2) void hgemm_k128(
    const __half* __restrict__ A, int lda, long long sA1, long long sA2,
    const __half* __restrict__ Bm, int ldb, long long sB1, long long sB2,
    __half* __restrict__ C, int ldc, long long sC1, long long sC2,
    float alpha, int Hdiv)
{
    extern __shared__ uint32_t sk[];
    uint32_t* As = sk;               // 128*68 u32
    uint32_t* Bs = sk + 128 * QR;

    int z = blockIdx.z;
    int zb = z / Hdiv, zh = z % Hdiv;
    const __half* Ab = A  + (size_t)zb * sA1 + (size_t)zh * sA2 + (size_t)(blockIdx.y * 128) * lda;
    const __half* Bb = Bm + (size_t)zb * sB1 + (size_t)zh * sB2 + (size_t)(blockIdx.x * 128) * ldb;
    __half*       Cb = C  + (size_t)zb * sC1 + (size_t)zh * sC2;

    int tid = threadIdx.x;
    int wid = tid >> 5, lane = tid & 31;
    int g = lane >> 2, tig = lane & 3;
    int warpM = wid >> 2, warpN = wid & 3;     // 2 x 4, warp tile 64x32

    #pragma unroll
    for (int i = 0; i < 8; i++) {
        int idx = i * 256 + tid;
        int row = idx >> 4, c16 = idx & 15;
        CP_ASYNC16(smem_u32(As + row * QR + c16 * 4), Ab + (size_t)row * lda + c16 * 8);
    }
    #pragma unroll
    for (int i = 0; i < 8; i++) {
        int idx = i * 256 + tid;
        int row = idx >> 4, c16 = idx & 15;
        CP_ASYNC16(smem_u32(Bs + row * QR + c16 * 4), Bb + (size_t)row * ldb + c16 * 8);
    }
    CP_COMMIT();

    uint32_t Aaddr = smem_u32(As) + ((warpM * 64 + (lane & 15)) * QR + (lane >> 4) * 4) * 4;
    uint32_t Baddr = smem_u32(Bs) + ((warpN * 32 + (lane >> 4) * 8 + (lane & 7)) * QR + ((lane >> 3) & 1) * 4) * 4;

    float acc[4][4][4];
    #pragma unroll
    for (int i = 0; i < 4; i++)
        #pragma unroll
        for (int j = 0; j < 4; j++)
            #pragma unroll
            for (int r = 0; r < 4; r++) acc[i][j][r] = 0.f;

    CP_WAIT0();
    __syncthreads();

    #pragma unroll
    for (int kk = 0; kk < 8; kk++) {
        uint32_t af[4][4];
        #pragma unroll
        for (int mt = 0; mt < 4; mt++)
            ldsm_x4(af[mt][0], af[mt][1], af[mt][2], af[mt][3],
                    Aaddr + mt * (16 * QR * 4) + kk * 32);
        uint32_t bf[4][2];
        ldsm_x4(bf[0][0], bf[0][1], bf[1][0], bf[1][1], Baddr + kk * 32);
        ldsm_x4(bf[2][0], bf[2][1], bf[3][0], bf[3][1], Baddr + 16 * QR * 4 + kk * 32);
        #pragma unroll
        for (int mt = 0; mt < 4; mt++)
            #pragma unroll
            for (int nt = 0; nt < 4; nt++)
                mma_fp16(acc[mt][nt], af[mt][0], af[mt][1], af[mt][2], af[mt][3],
                         bf[nt][0], bf[nt][1]);
    }

    #pragma unroll
    for (int mt = 0; mt < 4; mt++) {
        #pragma unroll
        for (int nt = 0; nt < 4; nt++) {
            int r0 = blockIdx.y * 128 + warpM * 64 + mt * 16 + g;
            int cN = blockIdx.x * 128 + warpN * 32 + nt * 8 + 2 * tig;
            #pragma unroll
            for (int hh = 0; hh < 2; hh++) {
                int rr = r0 + hh * 8;
                float e0 = acc[mt][nt][2 * hh + 0] * alpha;
                float e1 = acc[mt][nt][2 * hh + 1] * alpha;
                *(__half2*)(Cb + (size_t)rr * ldc + cN) = __floats2half2_rn(e0, e1);
            }
        }
    }
}

// ---------------- fp16 mma.sync GEMM (2-stage, SINGLE sync per k-tile) ----------------
// EPI: 0=alpha*acc ; 1=gelu(acc+bias) ; 2=acc+resid ; 3=acc+bias+resid ;
//      5=merged qkv (n0 < 2D: half store to C; n0 >= 2D: V^T scatter via 'resid' ptr)
#define W32 36
template<int EPI, bool OUTH>
__global__ __launch_bounds__(256, 2) void hgemm(
    const __half* __restrict__ A, int lda, long long sA1, long long sA2,
    const __half* __restrict__ Bm, int ldb, long long sB1, long long sB2,
    void* __restrict__ Cv, int ldc, long long sC1, long long sC2,
    int K, float alpha,
    const float* __restrict__ bias,
    const float* __restrict__ resid,
    int Hdiv)
{
    const int ASZ = 128 * W32;
    const int STG = 2 * ASZ;
    extern __shared__ uint32_t sm[];
    uint32_t* Abuf[2] = { sm,       sm + STG };
    uint32_t* Bbuf[2] = { sm + ASZ, sm + STG + ASZ };

    int z = blockIdx.z;
    int zb = z / Hdiv, zh = z % Hdiv;
    const __half* Ab = A  + (size_t)zb * sA1 + (size_t)zh * sA2;
    const __half* Bb = Bm + (size_t)zb * sB1 + (size_t)zh * sB2;

    int m0 = blockIdx.y * 128;
    int n0 = blockIdx.x * 128;
    int tid = threadIdx.x;
    int wid = tid >> 5, lane = tid & 31;
    int g = lane >> 2, tig = lane & 3;
    int warpM = wid >> 2, warpN = wid & 3;

    const __half* Abase = Ab + (size_t)m0 * lda;
    const __half* Bbase = Bb + (size_t)n0 * ldb;

    int aoff = ((warpM * 64 + (lane & 15)) * W32 + (lane >> 4) * 4) * 4;
    int boff = ((warpN * 32 + (lane >> 4) * 8 + (lane & 7)) * W32 + ((lane >> 3) & 1) * 4) * 4;

    float acc[4][4][4];
    #pragma unroll
    for (int i = 0; i < 4; i++)
        #pragma unroll
        for (int j = 0; j < 4; j++)
            #pragma unroll
            for (int r = 0; r < 4; r++) acc[i][j][r] = 0.f;

    int KT = K >> 6;

#define ISSUE_TILE(kt, bsel) do {                                              \
    const __half* Ag_ = Abase + (size_t)(kt) * 64;                             \
    const __half* Bg_ = Bbase + (size_t)(kt) * 64;                             \
    _Pragma("unroll")                                                          \
    for (int i_ = 0; i_ < 4; i_++) {                                           \
        int idx_ = i_ * 256 + tid;                                             \
        int row_ = idx_ >> 3, c8_ = idx_ & 7;                                  \
        uint32_t da_ = smem_u32(Abuf[bsel] + row_ * W32 + c8_ * 4);            \
        CP_ASYNC16(da_, Ag_ + (size_t)row_ * lda + c8_ * 8);                   \
    }                                                                          \
    _Pragma("unroll")                                                          \
    for (int i_ = 0; i_ < 4; i_++) {                                           \
        int idx_ = i_ * 256 + tid;                                             \
        int row_ = idx_ >> 3, c8_ = idx_ & 7;                                  \
        uint32_t db_ = smem_u32(Bbuf[bsel] + row_ * W32 + c8_ * 4);            \
        CP_ASYNC16(db_, Bg_ + (size_t)row_ * ldb + c8_ * 8);                   \
    }                                                                          \
    CP_COMMIT();                                                               \
} while (0)

    ISSUE_TILE(0, 0);

    for (int kt = 0; kt < KT; kt++) {
        int bsel = kt & 1;
        CP_WAIT0();          // tile kt arrived (only group outstanding)
        __syncthreads();     // publish tile kt; proves buf[bsel^1] readers done
        if (kt + 1 < KT) ISSUE_TILE(kt + 1, bsel ^ 1);

        uint32_t As_base = smem_u32(Abuf[bsel]) + aoff;
        uint32_t Bs_base = smem_u32(Bbuf[bsel]) + boff;
        #pragma unroll
        for (int kk = 0; kk < 4; kk++) {
            uint32_t As_a = As_base + kk * 32;
            uint32_t Bs_a = Bs_base + kk * 32;
            uint32_t af[4][4];
            #pragma unroll
            for (int mt = 0; mt < 4; mt++)
                ldsm_x4(af[mt][0], af[mt][1], af[mt][2], af[mt][3],
                        As_a + mt * (16 * W32 * 4));
            uint32_t bf[4][2];
            ldsm_x4(bf[0][0], bf[0][1], bf[1][0], bf[1][1], Bs_a);
            ldsm_x4(bf[2][0], bf[2][1], bf[3][0], bf[3][1], Bs_a + 16 * W32 * 4);
            #pragma unroll
            for (int mt = 0; mt < 4; mt++)
                #pragma unroll
                for (int nt = 0; nt < 4; nt++)
                    mma_fp16(acc[mt][nt], af[mt][0], af[mt][1], af[mt][2], af[mt][3],
                             bf[nt][0], bf[nt][1]);
        }
    }
#undef ISSUE_TILE

    float*  Cf = (float*)Cv  + (OUTH ? 0 : ((size_t)zb * sC1 + (size_t)zh * sC2));
    __half* Ch = (__half*)Cv + (OUTH ? ((size_t)zb * sC1 + (size_t)zh * sC2) : 0);
    __half* Vt = (__half*)resid;   // EPI==5 only
    #pragma unroll
    for (int mt = 0; mt < 4; mt++) {
        #pragma unroll
        for (int nt = 0; nt < 4; nt++) {
            int r0 = m0 + warpM * 64 + mt * 16 + g;
            int cN = n0 + warpN * 32 + nt * 8 + 2 * tig;
            #pragma unroll
            for (int hh = 0; hh < 2; hh++) {
                int rr = r0 + hh * 8;
                float e0 = acc[mt][nt][2 * hh + 0];
                float e1 = acc[mt][nt][2 * hh + 1];
                if (EPI == 0) { e0 *= alpha; e1 *= alpha; }
                if (EPI == 1 || EPI == 3) {
                    float2 bb = *(const float2*)(bias + cN);
                    e0 += bb.x; e1 += bb.y;
                }
                if (EPI == 1) { e0 = gelu_new_f(e0); e1 = gelu_new_f(e1); }
                if (EPI == 2 || EPI == 3) {
                    float2 rv = *(const float2*)(resid + (size_t)rr * ldc + cN);
                    e0 += rv.x; e1 += rv.y;
                }
                if (EPI == 5) {
                    if (n0 < 2 * D_) {
                        *(__half2*)(Ch + (size_t)rr * ldc + cN) = __floats2half2_rn(e0, e1);
                    } else {
                        int d = cN - 2 * D_;
                        int bidx = rr >> 11;            // rr / S_
                        int sloc = rr & (S_ - 1);
                        Vt[((size_t)bidx * D_ + d) * S_ + sloc]     = __float2half_rn(e0);
                        Vt[((size_t)bidx * D_ + d + 1) * S_ + sloc] = __float2half_rn(e1);
                    }
                } else if (OUTH) {
                    *(__half2*)(Ch + (size_t)rr * ldc + cN) = __floats2half2_rn(e0, e1);
                } else {
                    float2 st; st.x = e0; st.y = e1;
                    *(float2*)(Cf + (size_t)rr * ldc + cN) = st;
                }
            }
        }
    }
}

// ---------------- host ----------------
static const int DSM  = 2 * 2 * 128 * W32 * 4;   // 73728 bytes (hgemm)
static const int KDSM = 2 * 128 * QR * 4;        // 69632 bytes (hgemm_k128)

extern "C" void kernel_launch(void* const* d_in, const int* in_sizes, int n_in,
                              void* d_out, int out_size) {
    (void)in_sizes; (void)n_in; (void)out_size;
    const float* x    = (const float*)d_in[0];
    const float* wq   = (const float*)d_in[1];
    const float* wk   = (const float*)d_in[2];
    const float* wv   = (const float*)d_in[3];
    const float* wo   = (const float*)d_in[4];
    const float* ln1w = (const float*)d_in[5];
    const float* ln1b = (const float*)d_in[6];
    const float* ln2w = (const float*)d_in[7];
    const float* ln2b = (const float*)d_in[8];
    const float* fc1w = (const float*)d_in[9];
    const float* fc1b = (const float*)d_in[10];
    const float* fc2w = (const float*)d_in[11];
    const float* fc2b = (const float*)d_in[12];
    float* out = (float*)d_out;

    __half *h, *qkv, *vt, *o, *mid, *p, *sc;
    float *x1;
    __half *wqkvT, *woT, *fc1T, *fc2T;
    cudaGetSymbolAddress((void**)&h,     g_h);
    cudaGetSymbolAddress((void**)&qkv,   g_qkv);
    cudaGetSymbolAddress((void**)&vt,    g_vt);
    cudaGetSymbolAddress((void**)&o,     g_o);
    cudaGetSymbolAddress((void**)&x1,    g_x1);
    cudaGetSymbolAddress((void**)&mid,   g_mid);
    cudaGetSymbolAddress((void**)&sc,    g_sc);
    cudaGetSymbolAddress((void**)&p,     g_p);
    cudaGetSymbolAddress((void**)&wqkvT, g_wqkvT);
    cudaGetSymbolAddress((void**)&woT,   g_woT);
    cudaGetSymbolAddress((void**)&fc1T,  g_fc1T);
    cudaGetSymbolAddress((void**)&fc2T,  g_fc2T);

    cudaFuncSetAttribute(hgemm<5,true >, cudaFuncAttributeMaxDynamicSharedMemorySize, DSM);
    cudaFuncSetAttribute(hgemm<0,true >, cudaFuncAttributeMaxDynamicSharedMemorySize, DSM);
    cudaFuncSetAttribute(hgemm<2,false>, cudaFuncAttributeMaxDynamicSharedMemorySize, DSM);
    cudaFuncSetAttribute(hgemm<1,true >, cudaFuncAttributeMaxDynamicSharedMemorySize, DSM);
    cudaFuncSetAttribute(hgemm<3,false>, cudaFuncAttributeMaxDynamicSharedMemorySize, DSM);
    cudaFuncSetAttribute(hgemm_k128,     cudaFuncAttributeMaxDynamicSharedMemorySize, KDSM);

    dim3 blk(256);
    dim3 tb(32, 8);
    const long long SD3 = (long long)S_ * 3 * D_;
    const long long SD  = (long long)S_ * D_;
    const long long SS2 = (long long)S_ * S_;

    // launch order: index 3 = merged QKV GEMM (ncu profiles launch idx 3)
    ln_kernel<<<M_, 256>>>(x, ln1w, ln1b, h);                               // 0
    transpose3_k<<<dim3(D_/32, D_/32, 3), tb>>>(wq, wk, wv, wqkvT);          // 1
    transpose_k<<<dim3(D_/32, D_/32), tb>>>(wo, woT, D_, D_);               // 2

    // --- merged QKV projection: [M,2048] @ [6144,2048]^T -> q|k packed + V^T scatter ---
    dim3 gqkv(3 * D_ / 128, M_ / 128, 1);
    hgemm<5,true ><<<gqkv, blk, DSM>>>(h, D_, 0, 0, wqkvT, D_, 0, 0,
                                       qkv, 3 * D_, 0, 0, D_, 1.f, 0, (const float*)vt, 1);  // 3

    // --- scores = Q K^T / sqrt(HD) (fp16 out), one-shot K=128 kernel ---
    dim3 g2(S_ / 128, S_ / 128, B_ * H_);
    hgemm_k128<<<g2, blk, KDSM>>>(qkv,      3 * D_, SD3, HD_,
                                  qkv + D_, 3 * D_, SD3, HD_,
                                  sc, S_, (long long)H_ * SS2, SS2,
                                  0.08838834764831845f, H_);

    // --- softmax: warp-per-row, fp16 -> fp16 ---
    softmax_kernel<<<B_ * H_ * S_ / 8, 256>>>(sc, p);

    // --- O = P @ V  (B = V^T [HD, S] slices), fp16 out ---
    dim3 g3(HD_ / 128, S_ / 128, B_ * H_);
    hgemm<0,true ><<<g3, blk, DSM>>>(p, S_, (long long)H_ * SS2, SS2,
                                     vt, S_, (long long)D_ * S_, (long long)HD_ * S_,
                                     o,  D_, SD, HD_,
                                     S_, 1.f, 0, 0, H_);

    // --- out-projection + residual (fp32 residual stream) ---
    dim3 g1(D_ / 128, M_ / 128, 1);
    hgemm<2,false><<<g1, blk, DSM>>>(o, D_, 0, 0, woT, D_, 0, 0, x1, D_, 0, 0, D_, 1.f, 0, x, 1);

    // --- LN2 ---
    ln_kernel<<<M_, 256>>>(x1, ln2w, ln2b, h);

    // --- FC1 + bias + gelu (fp16 out) ---
    transpose_k<<<dim3(DFF_/32, D_/32), tb>>>(fc1w, fc1T, D_, DFF_);
    dim3 g4(DFF_ / 128, M_ / 128, 1);
    hgemm<1,true ><<<g4, blk, DSM>>>(h, D_, 0, 0, fc1T, D_, 0, 0, mid, DFF_, 0, 0, D_, 1.f, fc1b, 0, 1);

    // --- FC2 + bias + residual -> out (fp32) ---
    transpose_k<<<dim3(D_/32, DFF_/32), tb>>>(fc2w, fc2T, DFF_, D_);
    hgemm<3,false><<<g1, blk, DSM>>>(mid, DFF_, 0, 0, fc2T, DFF_, 0, 0, out, D_, 0, 0, DFF_, 1.f, fc2b, x1, 1);
}